// round 4
// baseline (speedup 1.0000x reference)
#include <cuda_runtime.h>
#include <math.h>

#define SEQ   2048
#define HEADS 24
#define CDIM  64
#define DDIM  256

// ---- scratch (static device allocations; no cudaMalloc anywhere) ----
__device__ float g_k[HEADS * SEQ * CDIM];      // [h][s][c]  12.6 MB
__device__ float g_q[HEADS * SEQ * CDIM];      // [h][s][c]  12.6 MB
__device__ float g_val[HEADS * SEQ * DDIM];    // [h][s][d]  50.3 MB
__device__ float g_part[HEADS * SEQ * DDIM];   // [h][s][d]  50.3 MB

// ============================================================================
// GEMM: C[s,n] = sum_k A[s,k] * W[n,k] + bias[n], scatter epilogue to k/q/val.
// BM=BN=128, BK=8, 256 threads, 8x8 micro-tile per thread.
// mode 0: n in [0,1024): h = head_base + n/128, c = n%128 (c<64 -> k else q)
// mode 1: n in [0,6144): h = n/256, d = n%256 -> g_val
// ============================================================================
__global__ void __launch_bounds__(256) gemm_scatter(
    const float* __restrict__ A, const float* __restrict__ W,
    const float* __restrict__ bias, int K, int mode, int head_base)
{
    __shared__ float As[8][132];
    __shared__ float Bs[8][132];

    const int tid = threadIdx.x;
    const int tx = tid & 15;        // 0..15 (col group)
    const int ty = tid >> 4;        // 0..15 (row group)
    const int row0 = blockIdx.y * 128;
    const int col0 = blockIdx.x * 128;

    const int lr = tid >> 1;        // 0..127 tile row for loads
    const int lk = (tid & 1) * 4;   // 0 or 4

    float acc[8][8];
#pragma unroll
    for (int i = 0; i < 8; i++)
#pragma unroll
        for (int j = 0; j < 8; j++) acc[i][j] = 0.0f;

    for (int k0 = 0; k0 < K; k0 += 8) {
        // load A tile (128 x 8), store transposed As[k][row]
        {
            float v0 = 0.f, v1 = 0.f, v2 = 0.f, v3 = 0.f;
            const float* src = A + (row0 + lr) * K + k0 + lk;
            if (k0 + lk + 4 <= K) {
                float4 f = *reinterpret_cast<const float4*>(src);
                v0 = f.x; v1 = f.y; v2 = f.z; v3 = f.w;
            } else {
                if (k0 + lk + 0 < K) v0 = src[0];
                if (k0 + lk + 1 < K) v1 = src[1];
                if (k0 + lk + 2 < K) v2 = src[2];
                if (k0 + lk + 3 < K) v3 = src[3];
            }
            As[lk + 0][lr] = v0; As[lk + 1][lr] = v1;
            As[lk + 2][lr] = v2; As[lk + 3][lr] = v3;
        }
        // load B tile = W rows (output cols), transposed Bs[k][col]
        {
            float v0 = 0.f, v1 = 0.f, v2 = 0.f, v3 = 0.f;
            const float* src = W + (col0 + lr) * K + k0 + lk;
            if (k0 + lk + 4 <= K) {
                float4 f = *reinterpret_cast<const float4*>(src);
                v0 = f.x; v1 = f.y; v2 = f.z; v3 = f.w;
            } else {
                if (k0 + lk + 0 < K) v0 = src[0];
                if (k0 + lk + 1 < K) v1 = src[1];
                if (k0 + lk + 2 < K) v2 = src[2];
                if (k0 + lk + 3 < K) v3 = src[3];
            }
            Bs[lk + 0][lr] = v0; Bs[lk + 1][lr] = v1;
            Bs[lk + 2][lr] = v2; Bs[lk + 3][lr] = v3;
        }
        __syncthreads();

#pragma unroll
        for (int kk = 0; kk < 8; kk++) {
            float a[8], b[8];
            float4 a0 = *reinterpret_cast<const float4*>(&As[kk][ty * 8]);
            float4 a1 = *reinterpret_cast<const float4*>(&As[kk][ty * 8 + 4]);
            float4 b0 = *reinterpret_cast<const float4*>(&Bs[kk][tx * 8]);
            float4 b1 = *reinterpret_cast<const float4*>(&Bs[kk][tx * 8 + 4]);
            a[0]=a0.x; a[1]=a0.y; a[2]=a0.z; a[3]=a0.w;
            a[4]=a1.x; a[5]=a1.y; a[6]=a1.z; a[7]=a1.w;
            b[0]=b0.x; b[1]=b0.y; b[2]=b0.z; b[3]=b0.w;
            b[4]=b1.x; b[5]=b1.y; b[6]=b1.z; b[7]=b1.w;
#pragma unroll
            for (int i = 0; i < 8; i++)
#pragma unroll
                for (int j = 0; j < 8; j++) acc[i][j] += a[i] * b[j];
        }
        __syncthreads();
    }

    // epilogue: bias + scatter
#pragma unroll
    for (int i = 0; i < 8; i++) {
        const int s = row0 + ty * 8 + i;
#pragma unroll
        for (int j = 0; j < 8; j++) {
            const int n = col0 + tx * 8 + j;
            float v = acc[i][j] + (bias ? bias[n] : 0.0f);
            if (mode == 0) {
                int h = head_base + (n >> 7);   // n/128
                int c = n & 127;
                if (c < 64) g_k[(h * SEQ + s) * CDIM + c] = v;
                else        g_q[(h * SEQ + s) * CDIM + (c - 64)] = v;
            } else {
                int h = n >> 8;                 // n/256
                int d = n & 255;
                g_val[(h * SEQ + s) * DDIM + d] = v;
            }
        }
    }
}

// ============================================================================
// Flash-attention per (i-tile of 32 rows, head). Single pass, online softmax.
// Block = 256 threads = 8 warps. Warp wy owns rows wy*4..wy*4+3 exclusively.
// Thread (wy, tx) accumulates out cols {tx + 32*cc, cc=0..7}.
// j-tile = 64. Q,K staged transposed (c-major) for conflict-free score GEMM.
// ============================================================================
#define KT_F   (64 * 33)
#define QT_F   (64 * 65)
#define VT_F   (64 * 260)
#define PS_F   (32 * 65)
#define ATTN_SMEM_BYTES ((KT_F + QT_F + VT_F + PS_F) * 4)

__global__ void __launch_bounds__(256) attn_kernel()
{
    extern __shared__ float sm[];
    float* Kt = sm;                  // [c][r]  64 x 33
    float* Qt = Kt + KT_F;           // [c][j]  64 x 65
    float* Vt = Qt + QT_F;           // [j][d]  64 x 260
    float* Ps = Vt + VT_F;           // [r][j]  32 x 65

    const int tid = threadIdx.x;
    const int tx = tid & 31;
    const int wy = tid >> 5;         // warp id 0..7
    const int i0 = blockIdx.x * 32;
    const int h  = blockIdx.y;

    const float* kbase = g_k   + h * SEQ * CDIM;
    const float* qbase = g_q   + h * SEQ * CDIM;
    const float* vbase = g_val + h * SEQ * DDIM;

    // stage K_i transposed, once per block
#pragma unroll
    for (int i = 0; i < 8; i++) {
        int idx = tid + i * 256;          // 0..2047
        int r = idx >> 6, c = idx & 63;
        Kt[c * 33 + r] = kbase[(i0 + r) * CDIM + c];
    }

    float acc[4][8];
#pragma unroll
    for (int rr = 0; rr < 4; rr++)
#pragma unroll
        for (int cc = 0; cc < 8; cc++) acc[rr][cc] = 0.0f;
    float m[4] = {-3.0e38f, -3.0e38f, -3.0e38f, -3.0e38f};
    float l[4] = {0.f, 0.f, 0.f, 0.f};

    const float SCALE = 0.35355339059327373f;   // 1/sqrt(8)

    for (int j0 = 0; j0 < SEQ; j0 += 64) {
        __syncthreads();   // previous tile fully consumed (also covers Kt init)

        // stage Q_j transposed [c][j]
#pragma unroll
        for (int i = 0; i < 4; i++) {
            int idx4 = tid + i * 256;         // 0..1023 float4s
            int j = idx4 >> 4;
            int c4 = (idx4 & 15) << 2;
            float4 f = *reinterpret_cast<const float4*>(
                qbase + (j0 + j) * CDIM + c4);
            Qt[(c4 + 0) * 65 + j] = f.x;
            Qt[(c4 + 1) * 65 + j] = f.y;
            Qt[(c4 + 2) * 65 + j] = f.z;
            Qt[(c4 + 3) * 65 + j] = f.w;
        }
        // stage V_j [j][d]
#pragma unroll
        for (int i = 0; i < 16; i++) {
            int idx4 = tid + i * 256;         // 0..4095 float4s
            int j = idx4 >> 6;
            int d4 = (idx4 & 63) << 2;
            *reinterpret_cast<float4*>(&Vt[j * 260 + d4]) =
                *reinterpret_cast<const float4*>(vbase + (j0 + j) * DDIM + d4);
        }
        __syncthreads();

        // scores: s[rr][{tx, tx+32}] = k[i0+wy*4+rr] . q[j0 + col]
        float s0[4] = {0.f, 0.f, 0.f, 0.f};
        float s1[4] = {0.f, 0.f, 0.f, 0.f};
#pragma unroll 8
        for (int c = 0; c < 64; c++) {
            float q0 = Qt[c * 65 + tx];
            float q1 = Qt[c * 65 + tx + 32];
#pragma unroll
            for (int rr = 0; rr < 4; rr++) {
                float kv = Kt[c * 33 + wy * 4 + rr];
                s0[rr] += kv * q0;
                s1[rr] += kv * q1;
            }
        }

        // online softmax per row (warp-exclusive rows)
#pragma unroll
        for (int rr = 0; rr < 4; rr++) {
            float a = s0[rr] * SCALE, b = s1[rr] * SCALE;
            float tm = fmaxf(a, b);
#pragma unroll
            for (int off = 16; off > 0; off >>= 1)
                tm = fmaxf(tm, __shfl_xor_sync(0xffffffffu, tm, off));
            float mn = fmaxf(m[rr], tm);
            float alpha = __expf(m[rr] - mn);
            float p0 = __expf(a - mn);
            float p1 = __expf(b - mn);
            float rs = p0 + p1;
#pragma unroll
            for (int off = 16; off > 0; off >>= 1)
                rs += __shfl_xor_sync(0xffffffffu, rs, off);
            l[rr] = l[rr] * alpha + rs;
            m[rr] = mn;
            Ps[(wy * 4 + rr) * 65 + tx] = p0;
            Ps[(wy * 4 + rr) * 65 + tx + 32] = p1;
#pragma unroll
            for (int cc = 0; cc < 8; cc++) acc[rr][cc] *= alpha;
        }
        __syncwarp();

        // acc += P @ V   (P rows owned by this warp)
#pragma unroll 4
        for (int jj = 0; jj < 64; jj++) {
            float pv[4];
#pragma unroll
            for (int rr = 0; rr < 4; rr++)
                pv[rr] = Ps[(wy * 4 + rr) * 65 + jj];
#pragma unroll
            for (int cc = 0; cc < 8; cc++) {
                float v = Vt[jj * 260 + tx + 32 * cc];
#pragma unroll
                for (int rr = 0; rr < 4; rr++)
                    acc[rr][cc] += pv[rr] * v;
            }
        }
    }

    // normalize + write per-head partial
#pragma unroll
    for (int rr = 0; rr < 4; rr++) {
        float inv = 1.0f / l[rr];
        int s = i0 + wy * 4 + rr;
#pragma unroll
        for (int cc = 0; cc < 8; cc++)
            g_part[(h * SEQ + s) * DDIM + tx + 32 * cc] = acc[rr][cc] * inv;
    }
}

// ============================================================================
// Sum over the 24 heads.
// ============================================================================
__global__ void __launch_bounds__(256) reduce_heads(float* __restrict__ out)
{
    int i = blockIdx.x * blockDim.x + threadIdx.x;   // 0 .. SEQ*DDIM-1
    float s = 0.0f;
#pragma unroll
    for (int h = 0; h < HEADS; h++)
        s += g_part[h * SEQ * DDIM + i];
    out[i] = s;
}

// ============================================================================
// launch
// ============================================================================
extern "C" void kernel_launch(void* const* d_in, const int* in_sizes, int n_in,
                              void* d_out, int out_size)
{
    (void)in_sizes; (void)n_in; (void)out_size;
    const float* nodes   = (const float*)d_in[0];
    const float* aux     = (const float*)d_in[1];
    const float* rot     = (const float*)d_in[2];
    const float* W_nodes = (const float*)d_in[3];
    const float* b_nodes = (const float*)d_in[4];
    const float* W_aux   = (const float*)d_in[5];
    const float* b_aux   = (const float*)d_in[6];
    const float* W_rot   = (const float*)d_in[7];
    const float* W_val   = (const float*)d_in[8];
    const float* b_val   = (const float*)d_in[9];
    float* out = (float*)d_out;

    cudaFuncSetAttribute(attn_kernel,
                         cudaFuncAttributeMaxDynamicSharedMemorySize,
                         ATTN_SMEM_BYTES);

    // projections (scatter into head-major k/q/val scratch)
    gemm_scatter<<<dim3(1024 / 128, SEQ / 128), 256>>>(nodes, W_nodes, b_nodes, 256, 0, 0);
    gemm_scatter<<<dim3(1024 / 128, SEQ / 128), 256>>>(aux,   W_aux,   b_aux,   64,  0, 8);
    gemm_scatter<<<dim3(1024 / 128, SEQ / 128), 256>>>(rot,   W_rot,   nullptr, 4,   0, 16);
    gemm_scatter<<<dim3(6144 / 128, SEQ / 128), 256>>>(nodes, W_val,   b_val,   256, 1, 0);

    // attention per (i-tile, head)
    attn_kernel<<<dim3(SEQ / 32, HEADS), 256, ATTN_SMEM_BYTES>>>();

    // head sum
    reduce_heads<<<(SEQ * DDIM) / 256, 256>>>(out);
}

// round 5
// speedup vs baseline: 1.9762x; 1.9762x over previous
#include <cuda_runtime.h>
#include <math.h>

#define SEQ   2048
#define HEADS 24
#define CDIM  64
#define DDIM  256
#define SCALE 0.35355339059327373f   // 1/sqrt(8)

// ---- scratch (static device allocations; no cudaMalloc anywhere) ----
__device__ float g_k[HEADS * SEQ * CDIM];      // [h][s][c]  pre-scaled, tf32-rounded
__device__ float g_q[HEADS * SEQ * CDIM];      // [h][s][c]  tf32-rounded
__device__ float g_val[HEADS * SEQ * DDIM];    // [h][s][d]  tf32-rounded
__device__ float g_part[HEADS * SEQ * DDIM];   // [h][s][d]  per-head outputs

__device__ __forceinline__ float tf32r(float x) {
    unsigned u;
    asm("cvt.rna.tf32.f32 %0, %1;" : "=r"(u) : "f"(x));
    return __uint_as_float(u);
}

__device__ __forceinline__ void mma_tf32(float c[4],
    unsigned a0, unsigned a1, unsigned a2, unsigned a3,
    unsigned b0, unsigned b1)
{
    asm volatile(
        "mma.sync.aligned.m16n8k8.row.col.f32.tf32.tf32.f32 "
        "{%0,%1,%2,%3}, {%4,%5,%6,%7}, {%8,%9}, {%0,%1,%2,%3};"
        : "+f"(c[0]), "+f"(c[1]), "+f"(c[2]), "+f"(c[3])
        : "r"(a0), "r"(a1), "r"(a2), "r"(a3), "r"(b0), "r"(b1));
}

// ============================================================================
// GEMM: C[s,n] = sum_k A[s,k] * W[n,k] + bias[n], scatter epilogue to k/q/val.
// Epilogue now folds the 1/sqrt(H) scale into k and rounds everything to tf32
// so the attention mma consumes exact tf32 operands.
// ============================================================================
__global__ void __launch_bounds__(256) gemm_scatter(
    const float* __restrict__ A, const float* __restrict__ W,
    const float* __restrict__ bias, int K, int mode, int head_base)
{
    __shared__ float As[8][132];
    __shared__ float Bs[8][132];

    const int tid = threadIdx.x;
    const int tx = tid & 15;
    const int ty = tid >> 4;
    const int row0 = blockIdx.y * 128;
    const int col0 = blockIdx.x * 128;

    const int lr = tid >> 1;
    const int lk = (tid & 1) * 4;

    float acc[8][8];
#pragma unroll
    for (int i = 0; i < 8; i++)
#pragma unroll
        for (int j = 0; j < 8; j++) acc[i][j] = 0.0f;

    for (int k0 = 0; k0 < K; k0 += 8) {
        {
            float v0 = 0.f, v1 = 0.f, v2 = 0.f, v3 = 0.f;
            const float* src = A + (row0 + lr) * K + k0 + lk;
            if (k0 + lk + 4 <= K) {
                float4 f = *reinterpret_cast<const float4*>(src);
                v0 = f.x; v1 = f.y; v2 = f.z; v3 = f.w;
            } else {
                if (k0 + lk + 0 < K) v0 = src[0];
                if (k0 + lk + 1 < K) v1 = src[1];
                if (k0 + lk + 2 < K) v2 = src[2];
                if (k0 + lk + 3 < K) v3 = src[3];
            }
            As[lk + 0][lr] = v0; As[lk + 1][lr] = v1;
            As[lk + 2][lr] = v2; As[lk + 3][lr] = v3;
        }
        {
            float v0 = 0.f, v1 = 0.f, v2 = 0.f, v3 = 0.f;
            const float* src = W + (col0 + lr) * K + k0 + lk;
            if (k0 + lk + 4 <= K) {
                float4 f = *reinterpret_cast<const float4*>(src);
                v0 = f.x; v1 = f.y; v2 = f.z; v3 = f.w;
            } else {
                if (k0 + lk + 0 < K) v0 = src[0];
                if (k0 + lk + 1 < K) v1 = src[1];
                if (k0 + lk + 2 < K) v2 = src[2];
                if (k0 + lk + 3 < K) v3 = src[3];
            }
            Bs[lk + 0][lr] = v0; Bs[lk + 1][lr] = v1;
            Bs[lk + 2][lr] = v2; Bs[lk + 3][lr] = v3;
        }
        __syncthreads();

#pragma unroll
        for (int kk = 0; kk < 8; kk++) {
            float a[8], b[8];
            float4 a0 = *reinterpret_cast<const float4*>(&As[kk][ty * 8]);
            float4 a1 = *reinterpret_cast<const float4*>(&As[kk][ty * 8 + 4]);
            float4 b0 = *reinterpret_cast<const float4*>(&Bs[kk][tx * 8]);
            float4 b1 = *reinterpret_cast<const float4*>(&Bs[kk][tx * 8 + 4]);
            a[0]=a0.x; a[1]=a0.y; a[2]=a0.z; a[3]=a0.w;
            a[4]=a1.x; a[5]=a1.y; a[6]=a1.z; a[7]=a1.w;
            b[0]=b0.x; b[1]=b0.y; b[2]=b0.z; b[3]=b0.w;
            b[4]=b1.x; b[5]=b1.y; b[6]=b1.z; b[7]=b1.w;
#pragma unroll
            for (int i = 0; i < 8; i++)
#pragma unroll
                for (int j = 0; j < 8; j++) acc[i][j] += a[i] * b[j];
        }
        __syncthreads();
    }

#pragma unroll
    for (int i = 0; i < 8; i++) {
        const int s = row0 + ty * 8 + i;
#pragma unroll
        for (int j = 0; j < 8; j++) {
            const int n = col0 + tx * 8 + j;
            float v = acc[i][j] + (bias ? bias[n] : 0.0f);
            if (mode == 0) {
                int h = head_base + (n >> 7);
                int c = n & 127;
                if (c < 64) g_k[(h * SEQ + s) * CDIM + c] = tf32r(v * SCALE);
                else        g_q[(h * SEQ + s) * CDIM + (c - 64)] = tf32r(v);
            } else {
                int h = n >> 8;
                int d = n & 255;
                g_val[(h * SEQ + s) * DDIM + d] = tf32r(v);
            }
        }
    }
}

// ============================================================================
// Flash attention via mma.sync m16n8k8 tf32.
// Block: 64 i-rows x one head. 256 threads = 8 warps.
//  - Score phase (warps 0-3): warp wm owns m-tile [16wm,16wm+16) x all 64 j.
//    Full-row warp ownership -> softmax stats in registers, shfl-quad reduce.
//    Writes P (tf32-rounded) and per-row alpha to smem.
//  - AV phase (all 8 warps): warp w owns d-slice [32w,32w+32). A=P from smem,
//    B=V fragments loaded directly from global (L2-resident).
// Smem tiles stride 68 -> all fragment loads bank-conflict-free (bank==lane).
// ============================================================================
#define TSTR   68
#define SM_KT  0
#define SM_QT  (64 * TSTR)
#define SM_PS  (2 * 64 * TSTR)
#define SM_AL  (3 * 64 * TSTR)
#define SM_L   (SM_AL + 64)
#define ATTN_SMEM_BYTES ((SM_L + 64) * 4)

__global__ void __launch_bounds__(256) attn_mma()
{
    extern __shared__ float sm[];
    const int tid  = threadIdx.x;
    const int lane = tid & 31;
    const int wid  = tid >> 5;
    const int ty   = lane >> 2;   // 0..7
    const int tq   = lane & 3;    // 0..3
    const int i0   = blockIdx.x * 64;
    const int h    = blockIdx.y;

    const float* kb = g_k   + h * SEQ * CDIM;
    const float* qb = g_q   + h * SEQ * CDIM;
    const float* vb = g_val + h * SEQ * DDIM;

    // stage K tile once: 64 x 64 floats
#pragma unroll
    for (int i = 0; i < 4; i++) {
        int idx4 = tid + i * 256;            // 0..1023 float4 slots
        int r  = idx4 >> 4;
        int c4 = (idx4 & 15) << 2;
        float4 f = *reinterpret_cast<const float4*>(kb + (i0 + r) * CDIM + c4);
        *reinterpret_cast<float4*>(sm + SM_KT + r * TSTR + c4) = f;
    }

    float acc[4][4][4];
#pragma unroll
    for (int mt = 0; mt < 4; mt++)
#pragma unroll
        for (int nt = 0; nt < 4; nt++)
#pragma unroll
            for (int e = 0; e < 4; e++) acc[mt][nt][e] = 0.0f;

    float rowM[2] = {-1e30f, -1e30f};
    float rowL[2] = {0.0f, 0.0f};

    for (int j0 = 0; j0 < SEQ; j0 += 64) {
        // stage Q tile
#pragma unroll
        for (int i = 0; i < 4; i++) {
            int idx4 = tid + i * 256;
            int r  = idx4 >> 4;
            int c4 = (idx4 & 15) << 2;
            float4 f = *reinterpret_cast<const float4*>(qb + (j0 + r) * CDIM + c4);
            *reinterpret_cast<float4*>(sm + SM_QT + r * TSTR + c4) = f;
        }
        __syncthreads();   // staging visible; also fences prev-tile AV vs Ps/Alpha rewrite

        // ---------------- score phase: warps 0-3 ----------------
        if (wid < 4) {
            float sc[8][4];
#pragma unroll
            for (int nt = 0; nt < 8; nt++)
#pragma unroll
                for (int e = 0; e < 4; e++) sc[nt][e] = 0.0f;

#pragma unroll
            for (int kk = 0; kk < 8; kk++) {
                const float* ka = sm + SM_KT + (wid * 16 + ty) * TSTR + kk * 8 + tq;
                unsigned a0 = __float_as_uint(ka[0]);
                unsigned a2 = __float_as_uint(ka[4]);
                unsigned a1 = __float_as_uint(ka[8 * TSTR]);
                unsigned a3 = __float_as_uint(ka[8 * TSTR + 4]);
#pragma unroll
                for (int nt = 0; nt < 8; nt++) {
                    const float* qa = sm + SM_QT + (nt * 8 + ty) * TSTR + kk * 8 + tq;
                    unsigned b0 = __float_as_uint(qa[0]);
                    unsigned b1 = __float_as_uint(qa[4]);
                    mma_tf32(sc[nt], a0, a1, a2, a3, b0, b1);
                }
            }

            // softmax: rows rA = 16*wid+ty, rB = rA+8 (cols spread over quad lanes)
            float tmA = -1e30f, tmB = -1e30f;
#pragma unroll
            for (int nt = 0; nt < 8; nt++) {
                tmA = fmaxf(tmA, fmaxf(sc[nt][0], sc[nt][1]));
                tmB = fmaxf(tmB, fmaxf(sc[nt][2], sc[nt][3]));
            }
            tmA = fmaxf(tmA, __shfl_xor_sync(0xffffffffu, tmA, 1));
            tmA = fmaxf(tmA, __shfl_xor_sync(0xffffffffu, tmA, 2));
            tmB = fmaxf(tmB, __shfl_xor_sync(0xffffffffu, tmB, 1));
            tmB = fmaxf(tmB, __shfl_xor_sync(0xffffffffu, tmB, 2));

            float mnA = fmaxf(rowM[0], tmA);
            float mnB = fmaxf(rowM[1], tmB);
            float alA = __expf(rowM[0] - mnA);
            float alB = __expf(rowM[1] - mnB);

            float sumA = 0.0f, sumB = 0.0f;
            const int rA = wid * 16 + ty;
#pragma unroll
            for (int nt = 0; nt < 8; nt++) {
                float p0 = __expf(sc[nt][0] - mnA);
                float p1 = __expf(sc[nt][1] - mnA);
                float p2 = __expf(sc[nt][2] - mnB);
                float p3 = __expf(sc[nt][3] - mnB);
                sumA += p0 + p1;
                sumB += p2 + p3;
                float2 wa = make_float2(tf32r(p0), tf32r(p1));
                float2 wb = make_float2(tf32r(p2), tf32r(p3));
                *reinterpret_cast<float2*>(sm + SM_PS + rA * TSTR + nt * 8 + 2 * tq) = wa;
                *reinterpret_cast<float2*>(sm + SM_PS + (rA + 8) * TSTR + nt * 8 + 2 * tq) = wb;
            }
            sumA += __shfl_xor_sync(0xffffffffu, sumA, 1);
            sumA += __shfl_xor_sync(0xffffffffu, sumA, 2);
            sumB += __shfl_xor_sync(0xffffffffu, sumB, 1);
            sumB += __shfl_xor_sync(0xffffffffu, sumB, 2);

            rowL[0] = rowL[0] * alA + sumA;
            rowL[1] = rowL[1] * alB + sumB;
            rowM[0] = mnA;
            rowM[1] = mnB;
            if (tq == 0) {
                sm[SM_AL + rA]     = alA;
                sm[SM_AL + rA + 8] = alB;
            }
        }
        __syncthreads();   // P + alpha visible

        // ---------------- AV phase: all 8 warps, d-slice 32*wid ----------------
#pragma unroll
        for (int mt = 0; mt < 4; mt++) {
            float aA = sm[SM_AL + mt * 16 + ty];
            float aB = sm[SM_AL + mt * 16 + ty + 8];
#pragma unroll
            for (int nt = 0; nt < 4; nt++) {
                acc[mt][nt][0] *= aA; acc[mt][nt][1] *= aA;
                acc[mt][nt][2] *= aB; acc[mt][nt][3] *= aB;
            }
        }

        const float* vwp = vb + j0 * DDIM + wid * 32;
        unsigned bc[4][2];
#pragma unroll
        for (int nt = 0; nt < 4; nt++) {
            const float* p = vwp + tq * DDIM + nt * 8 + ty;
            bc[nt][0] = __float_as_uint(p[0]);
            bc[nt][1] = __float_as_uint(p[4 * DDIM]);
        }
#pragma unroll
        for (int kk = 0; kk < 8; kk++) {
            unsigned bn[4][2];
            if (kk < 7) {
#pragma unroll
                for (int nt = 0; nt < 4; nt++) {
                    const float* p = vwp + ((kk + 1) * 8 + tq) * DDIM + nt * 8 + ty;
                    bn[nt][0] = __float_as_uint(p[0]);
                    bn[nt][1] = __float_as_uint(p[4 * DDIM]);
                }
            }
#pragma unroll
            for (int mt = 0; mt < 4; mt++) {
                const float* pa = sm + SM_PS + (mt * 16 + ty) * TSTR + kk * 8 + tq;
                unsigned a0 = __float_as_uint(pa[0]);
                unsigned a2 = __float_as_uint(pa[4]);
                unsigned a1 = __float_as_uint(pa[8 * TSTR]);
                unsigned a3 = __float_as_uint(pa[8 * TSTR + 4]);
#pragma unroll
                for (int nt = 0; nt < 4; nt++)
                    mma_tf32(acc[mt][nt], a0, a1, a2, a3, bc[nt][0], bc[nt][1]);
            }
            if (kk < 7) {
#pragma unroll
                for (int nt = 0; nt < 4; nt++) {
                    bc[nt][0] = bn[nt][0];
                    bc[nt][1] = bn[nt][1];
                }
            }
        }
        // no sync needed here: next-iteration sync1 fences Ps/Alpha reuse
    }

    // publish L, then normalize and write per-head partials
    if (wid < 4 && tq == 0) {
        sm[SM_L + wid * 16 + ty]     = rowL[0];
        sm[SM_L + wid * 16 + ty + 8] = rowL[1];
    }
    __syncthreads();

    float* ob = g_part + (h * SEQ + i0) * DDIM + wid * 32;
#pragma unroll
    for (int mt = 0; mt < 4; mt++) {
        float iA = 1.0f / sm[SM_L + mt * 16 + ty];
        float iB = 1.0f / sm[SM_L + mt * 16 + ty + 8];
#pragma unroll
        for (int nt = 0; nt < 4; nt++) {
            float2 wa = make_float2(acc[mt][nt][0] * iA, acc[mt][nt][1] * iA);
            float2 wb = make_float2(acc[mt][nt][2] * iB, acc[mt][nt][3] * iB);
            *reinterpret_cast<float2*>(ob + (mt * 16 + ty) * DDIM + nt * 8 + 2 * tq) = wa;
            *reinterpret_cast<float2*>(ob + (mt * 16 + ty + 8) * DDIM + nt * 8 + 2 * tq) = wb;
        }
    }
}

// ============================================================================
// Sum over the 24 heads.
// ============================================================================
__global__ void __launch_bounds__(256) reduce_heads(float* __restrict__ out)
{
    int i = blockIdx.x * blockDim.x + threadIdx.x;
    float s = 0.0f;
#pragma unroll
    for (int h = 0; h < HEADS; h++)
        s += g_part[h * SEQ * DDIM + i];
    out[i] = s;
}

// ============================================================================
// launch
// ============================================================================
extern "C" void kernel_launch(void* const* d_in, const int* in_sizes, int n_in,
                              void* d_out, int out_size)
{
    (void)in_sizes; (void)n_in; (void)out_size;
    const float* nodes   = (const float*)d_in[0];
    const float* aux     = (const float*)d_in[1];
    const float* rot     = (const float*)d_in[2];
    const float* W_nodes = (const float*)d_in[3];
    const float* b_nodes = (const float*)d_in[4];
    const float* W_aux   = (const float*)d_in[5];
    const float* b_aux   = (const float*)d_in[6];
    const float* W_rot   = (const float*)d_in[7];
    const float* W_val   = (const float*)d_in[8];
    const float* b_val   = (const float*)d_in[9];
    float* out = (float*)d_out;

    cudaFuncSetAttribute(attn_mma,
                         cudaFuncAttributeMaxDynamicSharedMemorySize,
                         ATTN_SMEM_BYTES);

    // projections (scatter into head-major k/q/val scratch, tf32-rounded)
    gemm_scatter<<<dim3(1024 / 128, SEQ / 128), 256>>>(nodes, W_nodes, b_nodes, 256, 0, 0);
    gemm_scatter<<<dim3(1024 / 128, SEQ / 128), 256>>>(aux,   W_aux,   b_aux,   64,  0, 8);
    gemm_scatter<<<dim3(1024 / 128, SEQ / 128), 256>>>(rot,   W_rot,   nullptr, 4,   0, 16);
    gemm_scatter<<<dim3(6144 / 128, SEQ / 128), 256>>>(nodes, W_val,   b_val,   256, 1, 0);

    // tensor-core flash attention per (64-row i-tile, head)
    attn_mma<<<dim3(SEQ / 64, HEADS), 256, ATTN_SMEM_BYTES>>>();

    // head sum
    reduce_heads<<<(SEQ * DDIM) / 256, 256>>>(out);
}

// round 6
// speedup vs baseline: 2.7522x; 1.3927x over previous
#include <cuda_runtime.h>
#include <math.h>

#define SEQ   2048
#define HEADS 24
#define CDIM  64
#define DDIM  256
#define SCALE 0.35355339059327373f   // 1/sqrt(8)

// ---- scratch (static device allocations; no cudaMalloc anywhere) ----
__device__ float g_k[HEADS * SEQ * CDIM];      // [h][s][c]  pre-scaled, tf32-rounded
__device__ float g_q[HEADS * SEQ * CDIM];      // [h][s][c]  tf32-rounded
__device__ float g_val[HEADS * SEQ * DDIM];    // [h][s][d]  tf32-rounded
__device__ float g_part[HEADS * SEQ * DDIM];   // [h][s][d]  per-head outputs

__device__ __forceinline__ float tf32r(float x) {
    unsigned u;
    asm("cvt.rna.tf32.f32 %0, %1;" : "=r"(u) : "f"(x));
    return __uint_as_float(u);
}

__device__ __forceinline__ void mma_tf32(float c[4],
    unsigned a0, unsigned a1, unsigned a2, unsigned a3,
    unsigned b0, unsigned b1)
{
    asm volatile(
        "mma.sync.aligned.m16n8k8.row.col.f32.tf32.tf32.f32 "
        "{%0,%1,%2,%3}, {%4,%5,%6,%7}, {%8,%9}, {%0,%1,%2,%3};"
        : "+f"(c[0]), "+f"(c[1]), "+f"(c[2]), "+f"(c[3])
        : "r"(a0), "r"(a1), "r"(a2), "r"(a3), "r"(b0), "r"(b1));
}

// ============================================================================
// GEMM body: C[s,n] = sum_k A[s,k] * W[n,k] + bias[n], scatter to k/q/val.
// Epilogue folds 1/sqrt(H) into k and rounds to tf32.
// ============================================================================
__device__ __forceinline__ void gemm_body(
    const float* __restrict__ A, const float* __restrict__ W,
    const float* __restrict__ bias, int K, int mode, int head_base)
{
    __shared__ float As[8][132];
    __shared__ float Bs[8][132];

    const int tid = threadIdx.x;
    const int tx = tid & 15;
    const int ty = tid >> 4;
    const int row0 = blockIdx.y * 128;
    const int col0 = blockIdx.x * 128;

    const int lr = tid >> 1;
    const int lk = (tid & 1) * 4;

    float acc[8][8];
#pragma unroll
    for (int i = 0; i < 8; i++)
#pragma unroll
        for (int j = 0; j < 8; j++) acc[i][j] = 0.0f;

    for (int k0 = 0; k0 < K; k0 += 8) {
        {
            float v0 = 0.f, v1 = 0.f, v2 = 0.f, v3 = 0.f;
            const float* src = A + (row0 + lr) * K + k0 + lk;
            if (k0 + lk + 4 <= K) {
                float4 f = *reinterpret_cast<const float4*>(src);
                v0 = f.x; v1 = f.y; v2 = f.z; v3 = f.w;
            } else {
                if (k0 + lk + 0 < K) v0 = src[0];
                if (k0 + lk + 1 < K) v1 = src[1];
                if (k0 + lk + 2 < K) v2 = src[2];
                if (k0 + lk + 3 < K) v3 = src[3];
            }
            As[lk + 0][lr] = v0; As[lk + 1][lr] = v1;
            As[lk + 2][lr] = v2; As[lk + 3][lr] = v3;
        }
        {
            float v0 = 0.f, v1 = 0.f, v2 = 0.f, v3 = 0.f;
            const float* src = W + (col0 + lr) * K + k0 + lk;
            if (k0 + lk + 4 <= K) {
                float4 f = *reinterpret_cast<const float4*>(src);
                v0 = f.x; v1 = f.y; v2 = f.z; v3 = f.w;
            } else {
                if (k0 + lk + 0 < K) v0 = src[0];
                if (k0 + lk + 1 < K) v1 = src[1];
                if (k0 + lk + 2 < K) v2 = src[2];
                if (k0 + lk + 3 < K) v3 = src[3];
            }
            Bs[lk + 0][lr] = v0; Bs[lk + 1][lr] = v1;
            Bs[lk + 2][lr] = v2; Bs[lk + 3][lr] = v3;
        }
        __syncthreads();

#pragma unroll
        for (int kk = 0; kk < 8; kk++) {
            float a[8], b[8];
            float4 a0 = *reinterpret_cast<const float4*>(&As[kk][ty * 8]);
            float4 a1 = *reinterpret_cast<const float4*>(&As[kk][ty * 8 + 4]);
            float4 b0 = *reinterpret_cast<const float4*>(&Bs[kk][tx * 8]);
            float4 b1 = *reinterpret_cast<const float4*>(&Bs[kk][tx * 8 + 4]);
            a[0]=a0.x; a[1]=a0.y; a[2]=a0.z; a[3]=a0.w;
            a[4]=a1.x; a[5]=a1.y; a[6]=a1.z; a[7]=a1.w;
            b[0]=b0.x; b[1]=b0.y; b[2]=b0.z; b[3]=b0.w;
            b[4]=b1.x; b[5]=b1.y; b[6]=b1.z; b[7]=b1.w;
#pragma unroll
            for (int i = 0; i < 8; i++)
#pragma unroll
                for (int j = 0; j < 8; j++) acc[i][j] += a[i] * b[j];
        }
        __syncthreads();
    }

#pragma unroll
    for (int i = 0; i < 8; i++) {
        const int s = row0 + ty * 8 + i;
#pragma unroll
        for (int j = 0; j < 8; j++) {
            const int n = col0 + tx * 8 + j;
            float v = acc[i][j] + (bias ? bias[n] : 0.0f);
            if (mode == 0) {
                int h = head_base + (n >> 7);
                int c = n & 127;
                if (c < 64) g_k[(h * SEQ + s) * CDIM + c] = tf32r(v * SCALE);
                else        g_q[(h * SEQ + s) * CDIM + (c - 64)] = tf32r(v);
            } else {
                int h = n >> 8;
                int d = n & 255;
                g_val[(h * SEQ + s) * DDIM + d] = tf32r(v);
            }
        }
    }
}

// Combined kq projections: blockIdx.z selects source (nodes/aux/rot) so the
// three sub-wave GEMMs fill the chip concurrently in one launch.
__global__ void __launch_bounds__(256, 2) kq_gemm(
    const float* __restrict__ nodes, const float* __restrict__ Wn, const float* __restrict__ bn,
    const float* __restrict__ aux,   const float* __restrict__ Wa, const float* __restrict__ ba,
    const float* __restrict__ rot,   const float* __restrict__ Wr)
{
    if (blockIdx.z == 0)       gemm_body(nodes, Wn, bn,      256, 0, 0);
    else if (blockIdx.z == 1)  gemm_body(aux,   Wa, ba,      64,  0, 8);
    else                       gemm_body(rot,   Wr, nullptr, 4,   0, 16);
}

__global__ void __launch_bounds__(256, 2) val_gemm(
    const float* __restrict__ nodes, const float* __restrict__ Wv,
    const float* __restrict__ bv)
{
    gemm_body(nodes, Wv, bv, 256, 1, 0);
}

// ============================================================================
// Flash attention via mma.sync m16n8k8 tf32.
// Block: 64 i-rows x one head. 256 threads = 8 warps.
//  - Phase A (overlapped): warps 0-3 score+softmax (warp wm owns 16 rows,
//    stats in registers, quad shfl reduce); warps 4-7 stage the V tile
//    (64x256 f32) GMEM->SMEM with coalesced float4 copies.
//  - Phase B: all 8 warps AV; warp w owns d-slice [32w,32w+32). A=P from smem,
//    B=V from smem (stride 264 -> bank-conflict-free fragment loads).
//  - Next tile's Q is prefetched into registers during phase B.
// ============================================================================
#define TSTR   68
#define VSTR   264
#define SM_KT  0
#define SM_QT  (64 * TSTR)
#define SM_PS  (2 * 64 * TSTR)
#define SM_VT  (3 * 64 * TSTR)
#define SM_AL  (SM_VT + 64 * VSTR)
#define SM_L   (SM_AL + 64)
#define ATTN_SMEM_BYTES ((SM_L + 64) * 4)

__global__ void __launch_bounds__(256) attn_mma()
{
    extern __shared__ float sm[];
    const int tid  = threadIdx.x;
    const int lane = tid & 31;
    const int wid  = tid >> 5;
    const int ty   = lane >> 2;   // 0..7
    const int tq   = lane & 3;    // 0..3
    const int i0   = blockIdx.x * 64;
    const int h    = blockIdx.y;

    const float* kb = g_k   + h * SEQ * CDIM;
    const float* qb = g_q   + h * SEQ * CDIM;
    const float* vb = g_val + h * SEQ * DDIM;

    // stage K tile once: 64 x 64 floats
#pragma unroll
    for (int i = 0; i < 4; i++) {
        int idx4 = tid + i * 256;
        int r  = idx4 >> 4;
        int c4 = (idx4 & 15) << 2;
        float4 f = *reinterpret_cast<const float4*>(kb + (i0 + r) * CDIM + c4);
        *reinterpret_cast<float4*>(sm + SM_KT + r * TSTR + c4) = f;
    }

    float acc[4][4][4];
#pragma unroll
    for (int mt = 0; mt < 4; mt++)
#pragma unroll
        for (int nt = 0; nt < 4; nt++)
#pragma unroll
            for (int e = 0; e < 4; e++) acc[mt][nt][e] = 0.0f;

    float rowM[2] = {-1e30f, -1e30f};
    float rowL[2] = {0.0f, 0.0f};

    // prefetch Q tile 0 into registers
    float4 qreg[4];
#pragma unroll
    for (int i = 0; i < 4; i++) {
        int idx4 = tid + i * 256;
        int r  = idx4 >> 4;
        int c4 = (idx4 & 15) << 2;
        qreg[i] = *reinterpret_cast<const float4*>(qb + r * CDIM + c4);
    }

    for (int j0 = 0; j0 < SEQ; j0 += 64) {
        // commit prefetched Q tile to smem
#pragma unroll
        for (int i = 0; i < 4; i++) {
            int idx4 = tid + i * 256;
            int r  = idx4 >> 4;
            int c4 = (idx4 & 15) << 2;
            *reinterpret_cast<float4*>(sm + SM_QT + r * TSTR + c4) = qreg[i];
        }
        __syncthreads();   // Q visible; prev-tile AV done with Ps/Alpha/Vt

        if (wid < 4) {
            // ---------------- score + softmax (warps 0-3) ----------------
            float sc[8][4];
#pragma unroll
            for (int nt = 0; nt < 8; nt++)
#pragma unroll
                for (int e = 0; e < 4; e++) sc[nt][e] = 0.0f;

#pragma unroll
            for (int kk = 0; kk < 8; kk++) {
                const float* ka = sm + SM_KT + (wid * 16 + ty) * TSTR + kk * 8 + tq;
                unsigned a0 = __float_as_uint(ka[0]);
                unsigned a2 = __float_as_uint(ka[4]);
                unsigned a1 = __float_as_uint(ka[8 * TSTR]);
                unsigned a3 = __float_as_uint(ka[8 * TSTR + 4]);
#pragma unroll
                for (int nt = 0; nt < 8; nt++) {
                    const float* qa = sm + SM_QT + (nt * 8 + ty) * TSTR + kk * 8 + tq;
                    unsigned b0 = __float_as_uint(qa[0]);
                    unsigned b1 = __float_as_uint(qa[4]);
                    mma_tf32(sc[nt], a0, a1, a2, a3, b0, b1);
                }
            }

            float tmA = -1e30f, tmB = -1e30f;
#pragma unroll
            for (int nt = 0; nt < 8; nt++) {
                tmA = fmaxf(tmA, fmaxf(sc[nt][0], sc[nt][1]));
                tmB = fmaxf(tmB, fmaxf(sc[nt][2], sc[nt][3]));
            }
            tmA = fmaxf(tmA, __shfl_xor_sync(0xffffffffu, tmA, 1));
            tmA = fmaxf(tmA, __shfl_xor_sync(0xffffffffu, tmA, 2));
            tmB = fmaxf(tmB, __shfl_xor_sync(0xffffffffu, tmB, 1));
            tmB = fmaxf(tmB, __shfl_xor_sync(0xffffffffu, tmB, 2));

            float mnA = fmaxf(rowM[0], tmA);
            float mnB = fmaxf(rowM[1], tmB);
            float alA = __expf(rowM[0] - mnA);
            float alB = __expf(rowM[1] - mnB);

            float sumA = 0.0f, sumB = 0.0f;
            const int rA = wid * 16 + ty;
#pragma unroll
            for (int nt = 0; nt < 8; nt++) {
                float p0 = __expf(sc[nt][0] - mnA);
                float p1 = __expf(sc[nt][1] - mnA);
                float p2 = __expf(sc[nt][2] - mnB);
                float p3 = __expf(sc[nt][3] - mnB);
                sumA += p0 + p1;
                sumB += p2 + p3;
                float2 wa = make_float2(tf32r(p0), tf32r(p1));
                float2 wb = make_float2(tf32r(p2), tf32r(p3));
                *reinterpret_cast<float2*>(sm + SM_PS + rA * TSTR + nt * 8 + 2 * tq) = wa;
                *reinterpret_cast<float2*>(sm + SM_PS + (rA + 8) * TSTR + nt * 8 + 2 * tq) = wb;
            }
            sumA += __shfl_xor_sync(0xffffffffu, sumA, 1);
            sumA += __shfl_xor_sync(0xffffffffu, sumA, 2);
            sumB += __shfl_xor_sync(0xffffffffu, sumB, 1);
            sumB += __shfl_xor_sync(0xffffffffu, sumB, 2);

            rowL[0] = rowL[0] * alA + sumA;
            rowL[1] = rowL[1] * alB + sumB;
            rowM[0] = mnA;
            rowM[1] = mnB;
            if (tq == 0) {
                sm[SM_AL + rA]     = alA;
                sm[SM_AL + rA + 8] = alB;
            }
        } else {
            // ---------------- V tile loader (warps 4-7) ----------------
            const float* vsrc = vb + j0 * DDIM;
            const int base = (wid - 4) * 32 + lane;   // 0..127
#pragma unroll
            for (int i = 0; i < 32; i++) {
                int flat = base + i * 128;            // 0..4095 float4 units
                int j  = flat >> 6;
                int d4 = (flat & 63) << 2;
                float4 f = *reinterpret_cast<const float4*>(vsrc + j * DDIM + d4);
                *reinterpret_cast<float4*>(sm + SM_VT + j * VSTR + d4) = f;
            }
        }
        __syncthreads();   // P, alpha, V visible

        // prefetch next Q tile into registers (overlaps with AV mma work)
        if (j0 + 64 < SEQ) {
#pragma unroll
            for (int i = 0; i < 4; i++) {
                int idx4 = tid + i * 256;
                int r  = idx4 >> 4;
                int c4 = (idx4 & 15) << 2;
                qreg[i] = *reinterpret_cast<const float4*>(
                    qb + (j0 + 64 + r) * CDIM + c4);
            }
        }

        // ---------------- AV phase: all 8 warps, d-slice 32*wid ----------------
#pragma unroll
        for (int mt = 0; mt < 4; mt++) {
            float aA = sm[SM_AL + mt * 16 + ty];
            float aB = sm[SM_AL + mt * 16 + ty + 8];
#pragma unroll
            for (int nt = 0; nt < 4; nt++) {
                acc[mt][nt][0] *= aA; acc[mt][nt][1] *= aA;
                acc[mt][nt][2] *= aB; acc[mt][nt][3] *= aB;
            }
        }

        const float* vt = sm + SM_VT + wid * 32;
#pragma unroll
        for (int kk = 0; kk < 8; kk++) {
            unsigned bc[4][2];
#pragma unroll
            for (int nt = 0; nt < 4; nt++) {
                const float* p = vt + (kk * 8 + tq) * VSTR + nt * 8 + ty;
                bc[nt][0] = __float_as_uint(p[0]);
                bc[nt][1] = __float_as_uint(p[4 * VSTR]);
            }
#pragma unroll
            for (int mt = 0; mt < 4; mt++) {
                const float* pa = sm + SM_PS + (mt * 16 + ty) * TSTR + kk * 8 + tq;
                unsigned a0 = __float_as_uint(pa[0]);
                unsigned a2 = __float_as_uint(pa[4]);
                unsigned a1 = __float_as_uint(pa[8 * TSTR]);
                unsigned a3 = __float_as_uint(pa[8 * TSTR + 4]);
#pragma unroll
                for (int nt = 0; nt < 4; nt++)
                    mma_tf32(acc[mt][nt], a0, a1, a2, a3, bc[nt][0], bc[nt][1]);
            }
        }
        // no trailing sync: next iteration's first sync fences smem reuse
    }

    // publish L, then normalize and write per-head partials
    if (wid < 4 && tq == 0) {
        sm[SM_L + wid * 16 + ty]     = rowL[0];
        sm[SM_L + wid * 16 + ty + 8] = rowL[1];
    }
    __syncthreads();

    float* ob = g_part + (h * SEQ + i0) * DDIM + wid * 32;
#pragma unroll
    for (int mt = 0; mt < 4; mt++) {
        float iA = 1.0f / sm[SM_L + mt * 16 + ty];
        float iB = 1.0f / sm[SM_L + mt * 16 + ty + 8];
#pragma unroll
        for (int nt = 0; nt < 4; nt++) {
            float2 wa = make_float2(acc[mt][nt][0] * iA, acc[mt][nt][1] * iA);
            float2 wb = make_float2(acc[mt][nt][2] * iB, acc[mt][nt][3] * iB);
            *reinterpret_cast<float2*>(ob + (mt * 16 + ty) * DDIM + nt * 8 + 2 * tq) = wa;
            *reinterpret_cast<float2*>(ob + (mt * 16 + ty + 8) * DDIM + nt * 8 + 2 * tq) = wb;
        }
    }
}

// ============================================================================
// Sum over the 24 heads.
// ============================================================================
__global__ void __launch_bounds__(256) reduce_heads(float* __restrict__ out)
{
    int i = blockIdx.x * blockDim.x + threadIdx.x;
    float s = 0.0f;
#pragma unroll
    for (int h = 0; h < HEADS; h++)
        s += g_part[h * SEQ * DDIM + i];
    out[i] = s;
}

// ============================================================================
// launch
// ============================================================================
extern "C" void kernel_launch(void* const* d_in, const int* in_sizes, int n_in,
                              void* d_out, int out_size)
{
    (void)in_sizes; (void)n_in; (void)out_size;
    const float* nodes   = (const float*)d_in[0];
    const float* aux     = (const float*)d_in[1];
    const float* rot     = (const float*)d_in[2];
    const float* W_nodes = (const float*)d_in[3];
    const float* b_nodes = (const float*)d_in[4];
    const float* W_aux   = (const float*)d_in[5];
    const float* b_aux   = (const float*)d_in[6];
    const float* W_rot   = (const float*)d_in[7];
    const float* W_val   = (const float*)d_in[8];
    const float* b_val   = (const float*)d_in[9];
    float* out = (float*)d_out;

    cudaFuncSetAttribute(attn_mma,
                         cudaFuncAttributeMaxDynamicSharedMemorySize,
                         ATTN_SMEM_BYTES);

    // projections (scatter into head-major k/q/val scratch, tf32-rounded)
    kq_gemm<<<dim3(1024 / 128, SEQ / 128, 3), 256>>>(
        nodes, W_nodes, b_nodes, aux, W_aux, b_aux, rot, W_rot);
    val_gemm<<<dim3(6144 / 128, SEQ / 128), 256>>>(nodes, W_val, b_val);

    // tensor-core flash attention per (64-row i-tile, head)
    attn_mma<<<dim3(SEQ / 64, HEADS), 256, ATTN_SMEM_BYTES>>>();

    // head sum
    reduce_heads<<<(SEQ * DDIM) / 256, 256>>>(out);
}

// round 9
// speedup vs baseline: 4.5692x; 1.6602x over previous
#include <cuda_runtime.h>
#include <math.h>

#define SEQ   2048
#define HEADS 24
#define CDIM  64
#define DDIM  256
#define SCALE 0.35355339059327373f   // 1/sqrt(8)

// ---- scratch (static device allocations; no cudaMalloc anywhere) ----
__device__ float g_k[HEADS * SEQ * CDIM];      // [h][s][c]  pre-scaled, tf32-rounded
__device__ float g_q[HEADS * SEQ * CDIM];      // [h][s][c]  tf32-rounded
__device__ float g_val[HEADS * SEQ * DDIM];    // [h][s][d]  tf32-rounded
__device__ float g_part[HEADS * SEQ * DDIM];   // [h][s][d]  per-head outputs

__device__ __forceinline__ float tf32r(float x) {
    unsigned u;
    asm("cvt.rna.tf32.f32 %0, %1;" : "=r"(u) : "f"(x));
    return __uint_as_float(u);
}

__device__ __forceinline__ void mma_tf32(float c[4],
    unsigned a0, unsigned a1, unsigned a2, unsigned a3,
    unsigned b0, unsigned b1)
{
    asm volatile(
        "mma.sync.aligned.m16n8k8.row.col.f32.tf32.tf32.f32 "
        "{%0,%1,%2,%3}, {%4,%5,%6,%7}, {%8,%9}, {%0,%1,%2,%3};"
        : "+f"(c[0]), "+f"(c[1]), "+f"(c[2]), "+f"(c[3])
        : "r"(a0), "r"(a1), "r"(a2), "r"(a3), "r"(b0), "r"(b1));
}

__device__ __forceinline__ unsigned smem_u32(const void* p) {
    unsigned a;
    asm("{ .reg .u64 t; cvta.to.shared.u64 t, %1; cvt.u32.u64 %0, t; }"
        : "=r"(a) : "l"(p));
    return a;
}

__device__ __forceinline__ void cp_async16(unsigned dst, const void* src) {
    asm volatile("cp.async.cg.shared.global [%0], [%1], 16;"
                 :: "r"(dst), "l"(src));
}
#define CP_ASYNC_COMMIT() asm volatile("cp.async.commit_group;" ::)
#define CP_ASYNC_WAIT0()  asm volatile("cp.async.wait_group 0;" ::: "memory")

// ============================================================================
// Tensor-core projection GEMM: C[s,n] = sum_k A[s,k]*W[n,k] + bias[n].
// Block tile 128x128, k-chunk 32 staged in smem (stride 36 -> fragment loads
// bank-conflict-free). Operands tf32-rounded at staging.
// Warp grid 4(m) x 2(n): warp tile 32x64, acc 2x8x4 regs.
// ============================================================================
#define GSTR 36

__device__ __forceinline__ void gscatter(int mode, int head_base,
                                         int s, int n, float v)
{
    if (mode == 0) {
        int h = head_base + (n >> 7);
        int c = n & 127;
        if (c < 64) g_k[(h * SEQ + s) * CDIM + c] = tf32r(v * SCALE);
        else        g_q[(h * SEQ + s) * CDIM + (c - 64)] = tf32r(v);
    } else {
        int h = n >> 8;
        int d = n & 255;
        g_val[(h * SEQ + s) * DDIM + d] = tf32r(v);
    }
}

__device__ __forceinline__ void mma_gemm(
    const float* __restrict__ A, const float* __restrict__ W,
    const float* __restrict__ bias, int K, int mode, int head_base)
{
    __shared__ float As[128 * GSTR];
    __shared__ float Bs[128 * GSTR];

    const int tid  = threadIdx.x;
    const int lane = tid & 31;
    const int wid  = tid >> 5;
    const int ty   = lane >> 2;
    const int tq   = lane & 3;
    const int wm   = wid & 3;      // m-warp 0..3  (32 rows each)
    const int wn   = wid >> 2;     // n-warp 0..1  (64 cols each)
    const int row0 = blockIdx.y * 128;
    const int col0 = blockIdx.x * 128;

    float acc[2][8][4];
#pragma unroll
    for (int mt = 0; mt < 2; mt++)
#pragma unroll
        for (int nt = 0; nt < 8; nt++)
#pragma unroll
            for (int e = 0; e < 4; e++) acc[mt][nt][e] = 0.0f;

    for (int k0 = 0; k0 < K; k0 += 32) {
        __syncthreads();
        const int rem = K - k0;
#pragma unroll
        for (int i = 0; i < 4; i++) {
            int flat = tid + i * 256;          // 0..1023
            int r  = flat >> 3;
            int c4 = (flat & 7) * 4;
            float4 fa = make_float4(0.f, 0.f, 0.f, 0.f);
            float4 fb = make_float4(0.f, 0.f, 0.f, 0.f);
            const float* pa = A + (row0 + r) * K + k0 + c4;
            const float* pb = W + (col0 + r) * K + k0 + c4;
            if (c4 + 4 <= rem) {
                fa = *reinterpret_cast<const float4*>(pa);
                fb = *reinterpret_cast<const float4*>(pb);
            } else {
                if (c4 + 0 < rem) { fa.x = pa[0]; fb.x = pb[0]; }
                if (c4 + 1 < rem) { fa.y = pa[1]; fb.y = pb[1]; }
                if (c4 + 2 < rem) { fa.z = pa[2]; fb.z = pb[2]; }
                if (c4 + 3 < rem) { fa.w = pa[3]; fb.w = pb[3]; }
            }
            fa.x = tf32r(fa.x); fa.y = tf32r(fa.y);
            fa.z = tf32r(fa.z); fa.w = tf32r(fa.w);
            fb.x = tf32r(fb.x); fb.y = tf32r(fb.y);
            fb.z = tf32r(fb.z); fb.w = tf32r(fb.w);
            *reinterpret_cast<float4*>(As + r * GSTR + c4) = fa;
            *reinterpret_cast<float4*>(Bs + r * GSTR + c4) = fb;
        }
        __syncthreads();

#pragma unroll
        for (int kk = 0; kk < 4; kk++) {
            unsigned b0[8], b1[8];
#pragma unroll
            for (int nt = 0; nt < 8; nt++) {
                const float* pb = Bs + (wn * 64 + nt * 8 + ty) * GSTR + kk * 8 + tq;
                b0[nt] = __float_as_uint(pb[0]);
                b1[nt] = __float_as_uint(pb[4]);
            }
#pragma unroll
            for (int mt = 0; mt < 2; mt++) {
                const float* pa = As + (wm * 32 + mt * 16 + ty) * GSTR + kk * 8 + tq;
                unsigned a0 = __float_as_uint(pa[0]);
                unsigned a2 = __float_as_uint(pa[4]);
                unsigned a1 = __float_as_uint(pa[8 * GSTR]);
                unsigned a3 = __float_as_uint(pa[8 * GSTR + 4]);
#pragma unroll
                for (int nt = 0; nt < 8; nt++)
                    mma_tf32(acc[mt][nt], a0, a1, a2, a3, b0[nt], b1[nt]);
            }
        }
    }

    // epilogue: bias + scatter
#pragma unroll
    for (int nt = 0; nt < 8; nt++) {
        int n = col0 + wn * 64 + nt * 8 + 2 * tq;
        float2 bb = make_float2(0.f, 0.f);
        if (bias) bb = *reinterpret_cast<const float2*>(bias + n);
#pragma unroll
        for (int mt = 0; mt < 2; mt++) {
            int s0 = row0 + wm * 32 + mt * 16 + ty;
            gscatter(mode, head_base, s0,     n,     acc[mt][nt][0] + bb.x);
            gscatter(mode, head_base, s0,     n + 1, acc[mt][nt][1] + bb.y);
            gscatter(mode, head_base, s0 + 8, n,     acc[mt][nt][2] + bb.x);
            gscatter(mode, head_base, s0 + 8, n + 1, acc[mt][nt][3] + bb.y);
        }
    }
}

__global__ void __launch_bounds__(256, 2) kq_gemm(
    const float* __restrict__ nodes, const float* __restrict__ Wn, const float* __restrict__ bn,
    const float* __restrict__ aux,   const float* __restrict__ Wa, const float* __restrict__ ba,
    const float* __restrict__ rot,   const float* __restrict__ Wr)
{
    if (blockIdx.z == 0)       mma_gemm(nodes, Wn, bn,      256, 0, 0);
    else if (blockIdx.z == 1)  mma_gemm(aux,   Wa, ba,      64,  0, 8);
    else                       mma_gemm(rot,   Wr, nullptr, 4,   0, 16);
}

__global__ void __launch_bounds__(256, 2) val_gemm(
    const float* __restrict__ nodes, const float* __restrict__ Wv,
    const float* __restrict__ bv)
{
    mma_gemm(nodes, Wv, bv, 256, 1, 0);
}

// ============================================================================
// Flash attention via mma.sync m16n8k8 tf32.
// Block: 128 i-rows x one head. 256 threads = 8 warps. j-tile = 64.
//  - After sync1: V tile (64x256 = 4096 float4s) staged via cp.async.cg
//    (16 x 16B per thread, zero register cost); latency hidden behind the
//    score mma + softmax. wait_group 0 just before sync2.
//  - Score: all 8 warps, warp w owns rows [16w,16w+16); stats in registers.
//  - AV: warp w owns d-slice [32w,32w+32) for all 128 rows (acc 8x4x4).
//  - Next Q tile prefetched into registers during AV.
// ============================================================================
#define TSTR   68
#define VSTR   264
#define SM_KT  0
#define SM_QT  (128 * TSTR)
#define SM_PS  (SM_QT + 64 * TSTR)
#define SM_VT  (SM_PS + 128 * TSTR)
#define SM_AL  (SM_VT + 64 * VSTR)
#define SM_L   (SM_AL + 128)
#define ATTN_SMEM_BYTES ((SM_L + 128) * 4)

__global__ void __launch_bounds__(256) attn_mma()
{
    extern __shared__ float sm[];
    const int tid  = threadIdx.x;
    const int lane = tid & 31;
    const int wid  = tid >> 5;    // 0..7
    const int ty   = lane >> 2;   // 0..7
    const int tq   = lane & 3;    // 0..3
    const int i0   = blockIdx.x * 128;
    const int h    = blockIdx.y;

    const float* kb = g_k   + h * SEQ * CDIM;
    const float* qb = g_q   + h * SEQ * CDIM;
    const float* vb = g_val + h * SEQ * DDIM;

    // stage K tile once: 128 x 64 floats
#pragma unroll
    for (int i = 0; i < 8; i++) {
        int idx4 = tid + i * 256;            // 0..2047 float4 slots
        int r  = idx4 >> 4;
        int c4 = (idx4 & 15) << 2;
        float4 f = *reinterpret_cast<const float4*>(kb + (i0 + r) * CDIM + c4);
        *reinterpret_cast<float4*>(sm + SM_KT + r * TSTR + c4) = f;
    }

    float acc[8][4][4];
#pragma unroll
    for (int mt = 0; mt < 8; mt++)
#pragma unroll
        for (int nt = 0; nt < 4; nt++)
#pragma unroll
            for (int e = 0; e < 4; e++) acc[mt][nt][e] = 0.0f;

    float rowM[2] = {-1e30f, -1e30f};
    float rowL[2] = {0.0f, 0.0f};

    // prefetch Q tile 0
    float4 qreg[4];
#pragma unroll
    for (int i = 0; i < 4; i++) {
        int idx4 = tid + i * 256;
        int r  = idx4 >> 4;
        int c4 = (idx4 & 15) << 2;
        qreg[i] = *reinterpret_cast<const float4*>(qb + r * CDIM + c4);
    }

    for (int j0 = 0; j0 < SEQ; j0 += 64) {
        // commit prefetched Q tile
#pragma unroll
        for (int i = 0; i < 4; i++) {
            int idx4 = tid + i * 256;
            int r  = idx4 >> 4;
            int c4 = (idx4 & 15) << 2;
            *reinterpret_cast<float4*>(sm + SM_QT + r * TSTR + c4) = qreg[i];
        }
        __syncthreads();   // sync1: Q visible; prev-tile AV done with Ps/Vt/AL

        // stage V tile via cp.async: 4096 float4s total, 16 per thread
#pragma unroll
        for (int i = 0; i < 16; i++) {
            int flat = tid + i * 256;        // 0..4095 float4 units
            int j  = flat >> 6;              // 0..63
            int d4 = (flat & 63) << 2;       // 0..252
            cp_async16(smem_u32(sm + SM_VT + j * VSTR + d4),
                       vb + (j0 + j) * DDIM + d4);
        }
        CP_ASYNC_COMMIT();

        // ---------------- score: all 8 warps, rows [16*wid, 16*wid+16) ----
        float sc[8][4];
#pragma unroll
        for (int nt = 0; nt < 8; nt++)
#pragma unroll
            for (int e = 0; e < 4; e++) sc[nt][e] = 0.0f;

#pragma unroll
        for (int kk = 0; kk < 8; kk++) {
            const float* ka = sm + SM_KT + (wid * 16 + ty) * TSTR + kk * 8 + tq;
            unsigned a0 = __float_as_uint(ka[0]);
            unsigned a2 = __float_as_uint(ka[4]);
            unsigned a1 = __float_as_uint(ka[8 * TSTR]);
            unsigned a3 = __float_as_uint(ka[8 * TSTR + 4]);
#pragma unroll
            for (int nt = 0; nt < 8; nt++) {
                const float* qa = sm + SM_QT + (nt * 8 + ty) * TSTR + kk * 8 + tq;
                unsigned b0 = __float_as_uint(qa[0]);
                unsigned b1 = __float_as_uint(qa[4]);
                mma_tf32(sc[nt], a0, a1, a2, a3, b0, b1);
            }
        }

        // ---------------- softmax: rows rA = 16*wid+ty, rB = rA+8 ----------
        {
            float tmA = -1e30f, tmB = -1e30f;
#pragma unroll
            for (int nt = 0; nt < 8; nt++) {
                tmA = fmaxf(tmA, fmaxf(sc[nt][0], sc[nt][1]));
                tmB = fmaxf(tmB, fmaxf(sc[nt][2], sc[nt][3]));
            }
            tmA = fmaxf(tmA, __shfl_xor_sync(0xffffffffu, tmA, 1));
            tmA = fmaxf(tmA, __shfl_xor_sync(0xffffffffu, tmA, 2));
            tmB = fmaxf(tmB, __shfl_xor_sync(0xffffffffu, tmB, 1));
            tmB = fmaxf(tmB, __shfl_xor_sync(0xffffffffu, tmB, 2));

            float mnA = fmaxf(rowM[0], tmA);
            float mnB = fmaxf(rowM[1], tmB);
            float alA = __expf(rowM[0] - mnA);
            float alB = __expf(rowM[1] - mnB);

            float sumA = 0.0f, sumB = 0.0f;
            const int rA = wid * 16 + ty;
#pragma unroll
            for (int nt = 0; nt < 8; nt++) {
                float p0 = __expf(sc[nt][0] - mnA);
                float p1 = __expf(sc[nt][1] - mnA);
                float p2 = __expf(sc[nt][2] - mnB);
                float p3 = __expf(sc[nt][3] - mnB);
                sumA += p0 + p1;
                sumB += p2 + p3;
                float2 wa = make_float2(tf32r(p0), tf32r(p1));
                float2 wb = make_float2(tf32r(p2), tf32r(p3));
                *reinterpret_cast<float2*>(sm + SM_PS + rA * TSTR + nt * 8 + 2 * tq) = wa;
                *reinterpret_cast<float2*>(sm + SM_PS + (rA + 8) * TSTR + nt * 8 + 2 * tq) = wb;
            }
            sumA += __shfl_xor_sync(0xffffffffu, sumA, 1);
            sumA += __shfl_xor_sync(0xffffffffu, sumA, 2);
            sumB += __shfl_xor_sync(0xffffffffu, sumB, 1);
            sumB += __shfl_xor_sync(0xffffffffu, sumB, 2);

            rowL[0] = rowL[0] * alA + sumA;
            rowL[1] = rowL[1] * alB + sumB;
            rowM[0] = mnA;
            rowM[1] = mnB;
            if (tq == 0) {
                sm[SM_AL + rA]     = alA;
                sm[SM_AL + rA + 8] = alB;
            }
        }
        CP_ASYNC_WAIT0();
        __syncthreads();   // sync2: P, alpha, V visible

        // prefetch next Q tile (overlaps AV mma)
        if (j0 + 64 < SEQ) {
#pragma unroll
            for (int i = 0; i < 4; i++) {
                int idx4 = tid + i * 256;
                int r  = idx4 >> 4;
                int c4 = (idx4 & 15) << 2;
                qreg[i] = *reinterpret_cast<const float4*>(
                    qb + (j0 + 64 + r) * CDIM + c4);
            }
        }

        // ---------------- AV: warp owns d-slice [32*wid, 32*wid+32) --------
#pragma unroll
        for (int mt = 0; mt < 8; mt++) {
            float aA = sm[SM_AL + mt * 16 + ty];
            float aB = sm[SM_AL + mt * 16 + ty + 8];
#pragma unroll
            for (int nt = 0; nt < 4; nt++) {
                acc[mt][nt][0] *= aA; acc[mt][nt][1] *= aA;
                acc[mt][nt][2] *= aB; acc[mt][nt][3] *= aB;
            }
        }

        const float* vt = sm + SM_VT + wid * 32;
#pragma unroll
        for (int kk = 0; kk < 8; kk++) {
            unsigned bc[4][2];
#pragma unroll
            for (int nt = 0; nt < 4; nt++) {
                const float* p = vt + (kk * 8 + tq) * VSTR + nt * 8 + ty;
                bc[nt][0] = __float_as_uint(p[0]);
                bc[nt][1] = __float_as_uint(p[4 * VSTR]);
            }
#pragma unroll
            for (int mt = 0; mt < 8; mt++) {
                const float* pa = sm + SM_PS + (mt * 16 + ty) * TSTR + kk * 8 + tq;
                unsigned a0 = __float_as_uint(pa[0]);
                unsigned a2 = __float_as_uint(pa[4]);
                unsigned a1 = __float_as_uint(pa[8 * TSTR]);
                unsigned a3 = __float_as_uint(pa[8 * TSTR + 4]);
#pragma unroll
                for (int nt = 0; nt < 4; nt++)
                    mma_tf32(acc[mt][nt], a0, a1, a2, a3, bc[nt][0], bc[nt][1]);
            }
        }
        // no trailing sync: next iteration's sync1 fences smem reuse
    }

    // publish L, then normalize and write per-head partials
    if (tq == 0) {
        sm[SM_L + wid * 16 + ty]     = rowL[0];
        sm[SM_L + wid * 16 + ty + 8] = rowL[1];
    }
    __syncthreads();

    float* ob = g_part + (h * SEQ + i0) * DDIM + wid * 32;
#pragma unroll
    for (int mt = 0; mt < 8; mt++) {
        float iA = 1.0f / sm[SM_L + mt * 16 + ty];
        float iB = 1.0f / sm[SM_L + mt * 16 + ty + 8];
#pragma unroll
        for (int nt = 0; nt < 4; nt++) {
            float2 wa = make_float2(acc[mt][nt][0] * iA, acc[mt][nt][1] * iA);
            float2 wb = make_float2(acc[mt][nt][2] * iB, acc[mt][nt][3] * iB);
            *reinterpret_cast<float2*>(ob + (mt * 16 + ty) * DDIM + nt * 8 + 2 * tq) = wa;
            *reinterpret_cast<float2*>(ob + (mt * 16 + ty + 8) * DDIM + nt * 8 + 2 * tq) = wb;
        }
    }
}

// ============================================================================
// Sum over the 24 heads.
// ============================================================================
__global__ void __launch_bounds__(256) reduce_heads(float* __restrict__ out)
{
    int i = blockIdx.x * blockDim.x + threadIdx.x;
    float s = 0.0f;
#pragma unroll
    for (int h = 0; h < HEADS; h++)
        s += g_part[h * SEQ * DDIM + i];
    out[i] = s;
}

// ============================================================================
// launch
// ============================================================================
extern "C" void kernel_launch(void* const* d_in, const int* in_sizes, int n_in,
                              void* d_out, int out_size)
{
    (void)in_sizes; (void)n_in; (void)out_size;
    const float* nodes   = (const float*)d_in[0];
    const float* aux     = (const float*)d_in[1];
    const float* rot     = (const float*)d_in[2];
    const float* W_nodes = (const float*)d_in[3];
    const float* b_nodes = (const float*)d_in[4];
    const float* W_aux   = (const float*)d_in[5];
    const float* b_aux   = (const float*)d_in[6];
    const float* W_rot   = (const float*)d_in[7];
    const float* W_val   = (const float*)d_in[8];
    const float* b_val   = (const float*)d_in[9];
    float* out = (float*)d_out;

    cudaFuncSetAttribute(attn_mma,
                         cudaFuncAttributeMaxDynamicSharedMemorySize,
                         ATTN_SMEM_BYTES);

    // tensor-core projections (scatter into head-major k/q/val, tf32-rounded)
    kq_gemm<<<dim3(1024 / 128, SEQ / 128, 3), 256>>>(
        nodes, W_nodes, b_nodes, aux, W_aux, b_aux, rot, W_rot);
    val_gemm<<<dim3(6144 / 128, SEQ / 128), 256>>>(nodes, W_val, b_val);

    // tensor-core flash attention per (128-row i-tile, head)
    attn_mma<<<dim3(SEQ / 128, HEADS), 256, ATTN_SMEM_BYTES>>>();

    // head sum
    reduce_heads<<<(SEQ * DDIM) / 256, 256>>>(out);
}

// round 10
// speedup vs baseline: 4.5706x; 1.0003x over previous
#include <cuda_runtime.h>
#include <math.h>

#define SEQ   2048
#define HEADS 24
#define CDIM  64
#define DDIM  256
#define SCALE 0.35355339059327373f   // 1/sqrt(8)

// ---- scratch (static device allocations; no cudaMalloc anywhere) ----
__device__ float g_k[HEADS * SEQ * CDIM];      // [h][s][c]  pre-scaled, tf32-rounded
__device__ float g_q[HEADS * SEQ * CDIM];      // [h][s][c]  tf32-rounded
__device__ float g_val[HEADS * SEQ * DDIM];    // [h][s][d]  tf32-rounded
__device__ float g_part[HEADS * SEQ * DDIM];   // [h][s][d]  per-head outputs

__device__ __forceinline__ float tf32r(float x) {
    unsigned u;
    asm("cvt.rna.tf32.f32 %0, %1;" : "=r"(u) : "f"(x));
    return __uint_as_float(u);
}

__device__ __forceinline__ void mma_tf32(float c[4],
    unsigned a0, unsigned a1, unsigned a2, unsigned a3,
    unsigned b0, unsigned b1)
{
    asm volatile(
        "mma.sync.aligned.m16n8k8.row.col.f32.tf32.tf32.f32 "
        "{%0,%1,%2,%3}, {%4,%5,%6,%7}, {%8,%9}, {%0,%1,%2,%3};"
        : "+f"(c[0]), "+f"(c[1]), "+f"(c[2]), "+f"(c[3])
        : "r"(a0), "r"(a1), "r"(a2), "r"(a3), "r"(b0), "r"(b1));
}

__device__ __forceinline__ unsigned smem_u32(const void* p) {
    unsigned a;
    asm("{ .reg .u64 t; cvta.to.shared.u64 t, %1; cvt.u32.u64 %0, t; }"
        : "=r"(a) : "l"(p));
    return a;
}

__device__ __forceinline__ void cp_async16(unsigned dst, const void* src) {
    asm volatile("cp.async.cg.shared.global [%0], [%1], 16;"
                 :: "r"(dst), "l"(src));
}
#define CP_ASYNC_COMMIT() asm volatile("cp.async.commit_group;" ::)
#define CP_ASYNC_WAIT0()  asm volatile("cp.async.wait_group 0;" ::: "memory")

// ============================================================================
// Tensor-core projection GEMM: C[s,n] = sum_k A[s,k]*W[n,k] + bias[n].
// Block tile 128x128, k-chunk 32 staged in smem (stride 36 -> fragment loads
// bank-conflict-free). Operands tf32-rounded at staging.
// Warp grid 4(m) x 2(n): warp tile 32x64, acc 2x8x4 regs.
// ============================================================================
#define GSTR 36

__device__ __forceinline__ void gscatter(int mode, int head_base,
                                         int s, int n, float v)
{
    if (mode == 0) {
        int h = head_base + (n >> 7);
        int c = n & 127;
        if (c < 64) g_k[(h * SEQ + s) * CDIM + c] = tf32r(v * SCALE);
        else        g_q[(h * SEQ + s) * CDIM + (c - 64)] = tf32r(v);
    } else {
        int h = n >> 8;
        int d = n & 255;
        g_val[(h * SEQ + s) * DDIM + d] = tf32r(v);
    }
}

__device__ __forceinline__ void mma_gemm(
    const float* __restrict__ A, const float* __restrict__ W,
    const float* __restrict__ bias, int K, int mode, int head_base)
{
    __shared__ float As[128 * GSTR];
    __shared__ float Bs[128 * GSTR];

    const int tid  = threadIdx.x;
    const int lane = tid & 31;
    const int wid  = tid >> 5;
    const int ty   = lane >> 2;
    const int tq   = lane & 3;
    const int wm   = wid & 3;      // m-warp 0..3  (32 rows each)
    const int wn   = wid >> 2;     // n-warp 0..1  (64 cols each)
    const int row0 = blockIdx.y * 128;
    const int col0 = blockIdx.x * 128;

    float acc[2][8][4];
#pragma unroll
    for (int mt = 0; mt < 2; mt++)
#pragma unroll
        for (int nt = 0; nt < 8; nt++)
#pragma unroll
            for (int e = 0; e < 4; e++) acc[mt][nt][e] = 0.0f;

    for (int k0 = 0; k0 < K; k0 += 32) {
        __syncthreads();
        const int rem = K - k0;
#pragma unroll
        for (int i = 0; i < 4; i++) {
            int flat = tid + i * 256;          // 0..1023
            int r  = flat >> 3;
            int c4 = (flat & 7) * 4;
            float4 fa = make_float4(0.f, 0.f, 0.f, 0.f);
            float4 fb = make_float4(0.f, 0.f, 0.f, 0.f);
            const float* pa = A + (row0 + r) * K + k0 + c4;
            const float* pb = W + (col0 + r) * K + k0 + c4;
            if (c4 + 4 <= rem) {
                fa = *reinterpret_cast<const float4*>(pa);
                fb = *reinterpret_cast<const float4*>(pb);
            } else {
                if (c4 + 0 < rem) { fa.x = pa[0]; fb.x = pb[0]; }
                if (c4 + 1 < rem) { fa.y = pa[1]; fb.y = pb[1]; }
                if (c4 + 2 < rem) { fa.z = pa[2]; fb.z = pb[2]; }
                if (c4 + 3 < rem) { fa.w = pa[3]; fb.w = pb[3]; }
            }
            fa.x = tf32r(fa.x); fa.y = tf32r(fa.y);
            fa.z = tf32r(fa.z); fa.w = tf32r(fa.w);
            fb.x = tf32r(fb.x); fb.y = tf32r(fb.y);
            fb.z = tf32r(fb.z); fb.w = tf32r(fb.w);
            *reinterpret_cast<float4*>(As + r * GSTR + c4) = fa;
            *reinterpret_cast<float4*>(Bs + r * GSTR + c4) = fb;
        }
        __syncthreads();

#pragma unroll
        for (int kk = 0; kk < 4; kk++) {
            unsigned b0[8], b1[8];
#pragma unroll
            for (int nt = 0; nt < 8; nt++) {
                const float* pb = Bs + (wn * 64 + nt * 8 + ty) * GSTR + kk * 8 + tq;
                b0[nt] = __float_as_uint(pb[0]);
                b1[nt] = __float_as_uint(pb[4]);
            }
#pragma unroll
            for (int mt = 0; mt < 2; mt++) {
                const float* pa = As + (wm * 32 + mt * 16 + ty) * GSTR + kk * 8 + tq;
                unsigned a0 = __float_as_uint(pa[0]);
                unsigned a2 = __float_as_uint(pa[4]);
                unsigned a1 = __float_as_uint(pa[8 * GSTR]);
                unsigned a3 = __float_as_uint(pa[8 * GSTR + 4]);
#pragma unroll
                for (int nt = 0; nt < 8; nt++)
                    mma_tf32(acc[mt][nt], a0, a1, a2, a3, b0[nt], b1[nt]);
            }
        }
    }

    // epilogue: bias + scatter
#pragma unroll
    for (int nt = 0; nt < 8; nt++) {
        int n = col0 + wn * 64 + nt * 8 + 2 * tq;
        float2 bb = make_float2(0.f, 0.f);
        if (bias) bb = *reinterpret_cast<const float2*>(bias + n);
#pragma unroll
        for (int mt = 0; mt < 2; mt++) {
            int s0 = row0 + wm * 32 + mt * 16 + ty;
            gscatter(mode, head_base, s0,     n,     acc[mt][nt][0] + bb.x);
            gscatter(mode, head_base, s0,     n + 1, acc[mt][nt][1] + bb.y);
            gscatter(mode, head_base, s0 + 8, n,     acc[mt][nt][2] + bb.x);
            gscatter(mode, head_base, s0 + 8, n + 1, acc[mt][nt][3] + bb.y);
        }
    }
}

__global__ void __launch_bounds__(256, 2) kq_gemm(
    const float* __restrict__ nodes, const float* __restrict__ Wn, const float* __restrict__ bn,
    const float* __restrict__ aux,   const float* __restrict__ Wa, const float* __restrict__ ba,
    const float* __restrict__ rot,   const float* __restrict__ Wr)
{
    if (blockIdx.z == 0)       mma_gemm(nodes, Wn, bn,      256, 0, 0);
    else if (blockIdx.z == 1)  mma_gemm(aux,   Wa, ba,      64,  0, 8);
    else                       mma_gemm(rot,   Wr, nullptr, 4,   0, 16);
}

__global__ void __launch_bounds__(256, 2) val_gemm(
    const float* __restrict__ nodes, const float* __restrict__ Wv,
    const float* __restrict__ bv)
{
    mma_gemm(nodes, Wv, bv, 256, 1, 0);
}

// ============================================================================
// Flash attention via mma.sync m16n8k8 tf32.
// Block: 128 i-rows x one head. 256 threads = 8 warps. j-tile = 64.
//  - After sync1: V tile (64x256 = 4096 float4s) staged via cp.async.cg
//    (16 x 16B per thread, zero register cost); latency hidden behind the
//    score mma + softmax. wait_group 0 just before sync2.
//  - Score: all 8 warps, warp w owns rows [16w,16w+16); stats in registers.
//  - AV: warp w owns d-slice [32w,32w+32) for all 128 rows (acc 8x4x4).
//  - Next Q tile prefetched into registers during AV.
// ============================================================================
#define TSTR   68
#define VSTR   264
#define SM_KT  0
#define SM_QT  (128 * TSTR)
#define SM_PS  (SM_QT + 64 * TSTR)
#define SM_VT  (SM_PS + 128 * TSTR)
#define SM_AL  (SM_VT + 64 * VSTR)
#define SM_L   (SM_AL + 128)
#define ATTN_SMEM_BYTES ((SM_L + 128) * 4)

__global__ void __launch_bounds__(256) attn_mma()
{
    extern __shared__ float sm[];
    const int tid  = threadIdx.x;
    const int lane = tid & 31;
    const int wid  = tid >> 5;    // 0..7
    const int ty   = lane >> 2;   // 0..7
    const int tq   = lane & 3;    // 0..3
    const int i0   = blockIdx.x * 128;
    const int h    = blockIdx.y;

    const float* kb = g_k   + h * SEQ * CDIM;
    const float* qb = g_q   + h * SEQ * CDIM;
    const float* vb = g_val + h * SEQ * DDIM;

    // stage K tile once: 128 x 64 floats
#pragma unroll
    for (int i = 0; i < 8; i++) {
        int idx4 = tid + i * 256;            // 0..2047 float4 slots
        int r  = idx4 >> 4;
        int c4 = (idx4 & 15) << 2;
        float4 f = *reinterpret_cast<const float4*>(kb + (i0 + r) * CDIM + c4);
        *reinterpret_cast<float4*>(sm + SM_KT + r * TSTR + c4) = f;
    }

    float acc[8][4][4];
#pragma unroll
    for (int mt = 0; mt < 8; mt++)
#pragma unroll
        for (int nt = 0; nt < 4; nt++)
#pragma unroll
            for (int e = 0; e < 4; e++) acc[mt][nt][e] = 0.0f;

    float rowM[2] = {-1e30f, -1e30f};
    float rowL[2] = {0.0f, 0.0f};

    // prefetch Q tile 0
    float4 qreg[4];
#pragma unroll
    for (int i = 0; i < 4; i++) {
        int idx4 = tid + i * 256;
        int r  = idx4 >> 4;
        int c4 = (idx4 & 15) << 2;
        qreg[i] = *reinterpret_cast<const float4*>(qb + r * CDIM + c4);
    }

    for (int j0 = 0; j0 < SEQ; j0 += 64) {
        // commit prefetched Q tile
#pragma unroll
        for (int i = 0; i < 4; i++) {
            int idx4 = tid + i * 256;
            int r  = idx4 >> 4;
            int c4 = (idx4 & 15) << 2;
            *reinterpret_cast<float4*>(sm + SM_QT + r * TSTR + c4) = qreg[i];
        }
        __syncthreads();   // sync1: Q visible; prev-tile AV done with Ps/Vt/AL

        // stage V tile via cp.async: 4096 float4s total, 16 per thread
#pragma unroll
        for (int i = 0; i < 16; i++) {
            int flat = tid + i * 256;        // 0..4095 float4 units
            int j  = flat >> 6;              // 0..63
            int d4 = (flat & 63) << 2;       // 0..252
            cp_async16(smem_u32(sm + SM_VT + j * VSTR + d4),
                       vb + (j0 + j) * DDIM + d4);
        }
        CP_ASYNC_COMMIT();

        // ---------------- score: all 8 warps, rows [16*wid, 16*wid+16) ----
        float sc[8][4];
#pragma unroll
        for (int nt = 0; nt < 8; nt++)
#pragma unroll
            for (int e = 0; e < 4; e++) sc[nt][e] = 0.0f;

#pragma unroll
        for (int kk = 0; kk < 8; kk++) {
            const float* ka = sm + SM_KT + (wid * 16 + ty) * TSTR + kk * 8 + tq;
            unsigned a0 = __float_as_uint(ka[0]);
            unsigned a2 = __float_as_uint(ka[4]);
            unsigned a1 = __float_as_uint(ka[8 * TSTR]);
            unsigned a3 = __float_as_uint(ka[8 * TSTR + 4]);
#pragma unroll
            for (int nt = 0; nt < 8; nt++) {
                const float* qa = sm + SM_QT + (nt * 8 + ty) * TSTR + kk * 8 + tq;
                unsigned b0 = __float_as_uint(qa[0]);
                unsigned b1 = __float_as_uint(qa[4]);
                mma_tf32(sc[nt], a0, a1, a2, a3, b0, b1);
            }
        }

        // ---------------- softmax: rows rA = 16*wid+ty, rB = rA+8 ----------
        {
            float tmA = -1e30f, tmB = -1e30f;
#pragma unroll
            for (int nt = 0; nt < 8; nt++) {
                tmA = fmaxf(tmA, fmaxf(sc[nt][0], sc[nt][1]));
                tmB = fmaxf(tmB, fmaxf(sc[nt][2], sc[nt][3]));
            }
            tmA = fmaxf(tmA, __shfl_xor_sync(0xffffffffu, tmA, 1));
            tmA = fmaxf(tmA, __shfl_xor_sync(0xffffffffu, tmA, 2));
            tmB = fmaxf(tmB, __shfl_xor_sync(0xffffffffu, tmB, 1));
            tmB = fmaxf(tmB, __shfl_xor_sync(0xffffffffu, tmB, 2));

            float mnA = fmaxf(rowM[0], tmA);
            float mnB = fmaxf(rowM[1], tmB);
            float alA = __expf(rowM[0] - mnA);
            float alB = __expf(rowM[1] - mnB);

            float sumA = 0.0f, sumB = 0.0f;
            const int rA = wid * 16 + ty;
#pragma unroll
            for (int nt = 0; nt < 8; nt++) {
                float p0 = __expf(sc[nt][0] - mnA);
                float p1 = __expf(sc[nt][1] - mnA);
                float p2 = __expf(sc[nt][2] - mnB);
                float p3 = __expf(sc[nt][3] - mnB);
                sumA += p0 + p1;
                sumB += p2 + p3;
                float2 wa = make_float2(tf32r(p0), tf32r(p1));
                float2 wb = make_float2(tf32r(p2), tf32r(p3));
                *reinterpret_cast<float2*>(sm + SM_PS + rA * TSTR + nt * 8 + 2 * tq) = wa;
                *reinterpret_cast<float2*>(sm + SM_PS + (rA + 8) * TSTR + nt * 8 + 2 * tq) = wb;
            }
            sumA += __shfl_xor_sync(0xffffffffu, sumA, 1);
            sumA += __shfl_xor_sync(0xffffffffu, sumA, 2);
            sumB += __shfl_xor_sync(0xffffffffu, sumB, 1);
            sumB += __shfl_xor_sync(0xffffffffu, sumB, 2);

            rowL[0] = rowL[0] * alA + sumA;
            rowL[1] = rowL[1] * alB + sumB;
            rowM[0] = mnA;
            rowM[1] = mnB;
            if (tq == 0) {
                sm[SM_AL + rA]     = alA;
                sm[SM_AL + rA + 8] = alB;
            }
        }
        CP_ASYNC_WAIT0();
        __syncthreads();   // sync2: P, alpha, V visible

        // prefetch next Q tile (overlaps AV mma)
        if (j0 + 64 < SEQ) {
#pragma unroll
            for (int i = 0; i < 4; i++) {
                int idx4 = tid + i * 256;
                int r  = idx4 >> 4;
                int c4 = (idx4 & 15) << 2;
                qreg[i] = *reinterpret_cast<const float4*>(
                    qb + (j0 + 64 + r) * CDIM + c4);
            }
        }

        // ---------------- AV: warp owns d-slice [32*wid, 32*wid+32) --------
#pragma unroll
        for (int mt = 0; mt < 8; mt++) {
            float aA = sm[SM_AL + mt * 16 + ty];
            float aB = sm[SM_AL + mt * 16 + ty + 8];
#pragma unroll
            for (int nt = 0; nt < 4; nt++) {
                acc[mt][nt][0] *= aA; acc[mt][nt][1] *= aA;
                acc[mt][nt][2] *= aB; acc[mt][nt][3] *= aB;
            }
        }

        const float* vt = sm + SM_VT + wid * 32;
#pragma unroll
        for (int kk = 0; kk < 8; kk++) {
            unsigned bc[4][2];
#pragma unroll
            for (int nt = 0; nt < 4; nt++) {
                const float* p = vt + (kk * 8 + tq) * VSTR + nt * 8 + ty;
                bc[nt][0] = __float_as_uint(p[0]);
                bc[nt][1] = __float_as_uint(p[4 * VSTR]);
            }
#pragma unroll
            for (int mt = 0; mt < 8; mt++) {
                const float* pa = sm + SM_PS + (mt * 16 + ty) * TSTR + kk * 8 + tq;
                unsigned a0 = __float_as_uint(pa[0]);
                unsigned a2 = __float_as_uint(pa[4]);
                unsigned a1 = __float_as_uint(pa[8 * TSTR]);
                unsigned a3 = __float_as_uint(pa[8 * TSTR + 4]);
#pragma unroll
                for (int nt = 0; nt < 4; nt++)
                    mma_tf32(acc[mt][nt], a0, a1, a2, a3, bc[nt][0], bc[nt][1]);
            }
        }
        // no trailing sync: next iteration's sync1 fences smem reuse
    }

    // publish L, then normalize and write per-head partials
    if (tq == 0) {
        sm[SM_L + wid * 16 + ty]     = rowL[0];
        sm[SM_L + wid * 16 + ty + 8] = rowL[1];
    }
    __syncthreads();

    float* ob = g_part + (h * SEQ + i0) * DDIM + wid * 32;
#pragma unroll
    for (int mt = 0; mt < 8; mt++) {
        float iA = 1.0f / sm[SM_L + mt * 16 + ty];
        float iB = 1.0f / sm[SM_L + mt * 16 + ty + 8];
#pragma unroll
        for (int nt = 0; nt < 4; nt++) {
            float2 wa = make_float2(acc[mt][nt][0] * iA, acc[mt][nt][1] * iA);
            float2 wb = make_float2(acc[mt][nt][2] * iB, acc[mt][nt][3] * iB);
            *reinterpret_cast<float2*>(ob + (mt * 16 + ty) * DDIM + nt * 8 + 2 * tq) = wa;
            *reinterpret_cast<float2*>(ob + (mt * 16 + ty + 8) * DDIM + nt * 8 + 2 * tq) = wb;
        }
    }
}

// ============================================================================
// Sum over the 24 heads.
// ============================================================================
__global__ void __launch_bounds__(256) reduce_heads(float* __restrict__ out)
{
    int i = blockIdx.x * blockDim.x + threadIdx.x;
    float s = 0.0f;
#pragma unroll
    for (int h = 0; h < HEADS; h++)
        s += g_part[h * SEQ * DDIM + i];
    out[i] = s;
}

// ============================================================================
// launch
// ============================================================================
extern "C" void kernel_launch(void* const* d_in, const int* in_sizes, int n_in,
                              void* d_out, int out_size)
{
    (void)in_sizes; (void)n_in; (void)out_size;
    const float* nodes   = (const float*)d_in[0];
    const float* aux     = (const float*)d_in[1];
    const float* rot     = (const float*)d_in[2];
    const float* W_nodes = (const float*)d_in[3];
    const float* b_nodes = (const float*)d_in[4];
    const float* W_aux   = (const float*)d_in[5];
    const float* b_aux   = (const float*)d_in[6];
    const float* W_rot   = (const float*)d_in[7];
    const float* W_val   = (const float*)d_in[8];
    const float* b_val   = (const float*)d_in[9];
    float* out = (float*)d_out;

    cudaFuncSetAttribute(attn_mma,
                         cudaFuncAttributeMaxDynamicSharedMemorySize,
                         ATTN_SMEM_BYTES);

    // tensor-core projections (scatter into head-major k/q/val, tf32-rounded)
    kq_gemm<<<dim3(1024 / 128, SEQ / 128, 3), 256>>>(
        nodes, W_nodes, b_nodes, aux, W_aux, b_aux, rot, W_rot);
    val_gemm<<<dim3(6144 / 128, SEQ / 128), 256>>>(nodes, W_val, b_val);

    // tensor-core flash attention per (128-row i-tile, head)
    attn_mma<<<dim3(SEQ / 128, HEADS), 256, ATTN_SMEM_BYTES>>>();

    // head sum
    reduce_heads<<<(SEQ * DDIM) / 256, 256>>>(out);
}

// round 13
// speedup vs baseline: 5.7736x; 1.2632x over previous
#include <cuda_runtime.h>
#include <cuda_fp16.h>
#include <math.h>

#define SEQ   2048
#define HEADS 24
#define CDIM  64
#define DDIM  256
#define SCALE 0.35355339059327373f   // 1/sqrt(8)

// ---- scratch (static device allocations; no cudaMalloc anywhere) ----
__device__ float g_k[HEADS * SEQ * CDIM];      // [h][s][c] pre-scaled, tf32
__device__ float g_q[HEADS * SEQ * CDIM];      // [h][s][c] tf32
__device__ float g_val[HEADS * SEQ * DDIM];    // [h][s][d] tf32
__device__ __half g_valh[HEADS * DDIM * SEQ];  // [h][d][s] fp16 transposed
__device__ float g_part[HEADS * SEQ * DDIM];   // [h][s][d] per-head outputs

__device__ __forceinline__ float tf32r(float x) {
    unsigned u;
    asm("cvt.rna.tf32.f32 %0, %1;" : "=r"(u) : "f"(x));
    return __uint_as_float(u);
}

__device__ __forceinline__ unsigned f16x2_pack(float lo, float hi) {
    unsigned r;
    asm("cvt.rn.f16x2.f32 %0, %1, %2;" : "=r"(r) : "f"(hi), "f"(lo));
    return r;
}

__device__ __forceinline__ void mma_tf32(float c[4],
    unsigned a0, unsigned a1, unsigned a2, unsigned a3,
    unsigned b0, unsigned b1)
{
    asm volatile(
        "mma.sync.aligned.m16n8k8.row.col.f32.tf32.tf32.f32 "
        "{%0,%1,%2,%3}, {%4,%5,%6,%7}, {%8,%9}, {%0,%1,%2,%3};"
        : "+f"(c[0]), "+f"(c[1]), "+f"(c[2]), "+f"(c[3])
        : "r"(a0), "r"(a1), "r"(a2), "r"(a3), "r"(b0), "r"(b1));
}

__device__ __forceinline__ void mma_f16(float c[4],
    unsigned a0, unsigned a1, unsigned a2, unsigned a3,
    unsigned b0, unsigned b1)
{
    asm volatile(
        "mma.sync.aligned.m16n8k16.row.col.f32.f16.f16.f32 "
        "{%0,%1,%2,%3}, {%4,%5,%6,%7}, {%8,%9}, {%0,%1,%2,%3};"
        : "+f"(c[0]), "+f"(c[1]), "+f"(c[2]), "+f"(c[3])
        : "r"(a0), "r"(a1), "r"(a2), "r"(a3), "r"(b0), "r"(b1));
}

__device__ __forceinline__ unsigned smem_u32(const void* p) {
    unsigned a;
    asm("{ .reg .u64 t; cvta.to.shared.u64 t, %1; cvt.u32.u64 %0, t; }"
        : "=r"(a) : "l"(p));
    return a;
}

__device__ __forceinline__ void cp_async16(unsigned dst, const void* src) {
    asm volatile("cp.async.cg.shared.global [%0], [%1], 16;"
                 :: "r"(dst), "l"(src));
}
#define CP_ASYNC_COMMIT() asm volatile("cp.async.commit_group;" ::)
#define CP_ASYNC_WAIT0()  asm volatile("cp.async.wait_group 0;" ::: "memory")

// ============================================================================
// Tensor-core projection GEMM (unchanged)
// ============================================================================
#define GSTR 36

__device__ __forceinline__ void gscatter(int mode, int head_base,
                                         int s, int n, float v)
{
    if (mode == 0) {
        int h = head_base + (n >> 7);
        int c = n & 127;
        if (c < 64) g_k[(h * SEQ + s) * CDIM + c] = tf32r(v * SCALE);
        else        g_q[(h * SEQ + s) * CDIM + (c - 64)] = tf32r(v);
    } else {
        int h = n >> 8;
        int d = n & 255;
        g_val[(h * SEQ + s) * DDIM + d] = tf32r(v);
    }
}

__device__ __forceinline__ void mma_gemm(
    const float* __restrict__ A, const float* __restrict__ W,
    const float* __restrict__ bias, int K, int mode, int head_base)
{
    __shared__ float As[128 * GSTR];
    __shared__ float Bs[128 * GSTR];

    const int tid  = threadIdx.x;
    const int lane = tid & 31;
    const int wid  = tid >> 5;
    const int ty   = lane >> 2;
    const int tq   = lane & 3;
    const int wm   = wid & 3;
    const int wn   = wid >> 2;
    const int row0 = blockIdx.y * 128;
    const int col0 = blockIdx.x * 128;

    float acc[2][8][4];
#pragma unroll
    for (int mt = 0; mt < 2; mt++)
#pragma unroll
        for (int nt = 0; nt < 8; nt++)
#pragma unroll
            for (int e = 0; e < 4; e++) acc[mt][nt][e] = 0.0f;

    for (int k0 = 0; k0 < K; k0 += 32) {
        __syncthreads();
        const int rem = K - k0;
#pragma unroll
        for (int i = 0; i < 4; i++) {
            int flat = tid + i * 256;
            int r  = flat >> 3;
            int c4 = (flat & 7) * 4;
            float4 fa = make_float4(0.f, 0.f, 0.f, 0.f);
            float4 fb = make_float4(0.f, 0.f, 0.f, 0.f);
            const float* pa = A + (row0 + r) * K + k0 + c4;
            const float* pb = W + (col0 + r) * K + k0 + c4;
            if (c4 + 4 <= rem) {
                fa = *reinterpret_cast<const float4*>(pa);
                fb = *reinterpret_cast<const float4*>(pb);
            } else {
                if (c4 + 0 < rem) { fa.x = pa[0]; fb.x = pb[0]; }
                if (c4 + 1 < rem) { fa.y = pa[1]; fb.y = pb[1]; }
                if (c4 + 2 < rem) { fa.z = pa[2]; fb.z = pb[2]; }
                if (c4 + 3 < rem) { fa.w = pa[3]; fb.w = pb[3]; }
            }
            fa.x = tf32r(fa.x); fa.y = tf32r(fa.y);
            fa.z = tf32r(fa.z); fa.w = tf32r(fa.w);
            fb.x = tf32r(fb.x); fb.y = tf32r(fb.y);
            fb.z = tf32r(fb.z); fb.w = tf32r(fb.w);
            *reinterpret_cast<float4*>(As + r * GSTR + c4) = fa;
            *reinterpret_cast<float4*>(Bs + r * GSTR + c4) = fb;
        }
        __syncthreads();

#pragma unroll
        for (int kk = 0; kk < 4; kk++) {
            unsigned b0[8], b1[8];
#pragma unroll
            for (int nt = 0; nt < 8; nt++) {
                const float* pb = Bs + (wn * 64 + nt * 8 + ty) * GSTR + kk * 8 + tq;
                b0[nt] = __float_as_uint(pb[0]);
                b1[nt] = __float_as_uint(pb[4]);
            }
#pragma unroll
            for (int mt = 0; mt < 2; mt++) {
                const float* pa = As + (wm * 32 + mt * 16 + ty) * GSTR + kk * 8 + tq;
                unsigned a0 = __float_as_uint(pa[0]);
                unsigned a2 = __float_as_uint(pa[4]);
                unsigned a1 = __float_as_uint(pa[8 * GSTR]);
                unsigned a3 = __float_as_uint(pa[8 * GSTR + 4]);
#pragma unroll
                for (int nt = 0; nt < 8; nt++)
                    mma_tf32(acc[mt][nt], a0, a1, a2, a3, b0[nt], b1[nt]);
            }
        }
    }

#pragma unroll
    for (int nt = 0; nt < 8; nt++) {
        int n = col0 + wn * 64 + nt * 8 + 2 * tq;
        float2 bb = make_float2(0.f, 0.f);
        if (bias) bb = *reinterpret_cast<const float2*>(bias + n);
#pragma unroll
        for (int mt = 0; mt < 2; mt++) {
            int s0 = row0 + wm * 32 + mt * 16 + ty;
            gscatter(mode, head_base, s0,     n,     acc[mt][nt][0] + bb.x);
            gscatter(mode, head_base, s0,     n + 1, acc[mt][nt][1] + bb.y);
            gscatter(mode, head_base, s0 + 8, n,     acc[mt][nt][2] + bb.x);
            gscatter(mode, head_base, s0 + 8, n + 1, acc[mt][nt][3] + bb.y);
        }
    }
}

__global__ void __launch_bounds__(256, 2) kq_gemm(
    const float* __restrict__ nodes, const float* __restrict__ Wn, const float* __restrict__ bn,
    const float* __restrict__ aux,   const float* __restrict__ Wa, const float* __restrict__ ba,
    const float* __restrict__ rot,   const float* __restrict__ Wr)
{
    if (blockIdx.z == 0)       mma_gemm(nodes, Wn, bn,      256, 0, 0);
    else if (blockIdx.z == 1)  mma_gemm(aux,   Wa, ba,      64,  0, 8);
    else                       mma_gemm(rot,   Wr, nullptr, 4,   0, 16);
}

__global__ void __launch_bounds__(256, 2) val_gemm(
    const float* __restrict__ nodes, const float* __restrict__ Wv,
    const float* __restrict__ bv)
{
    mma_gemm(nodes, Wv, bv, 256, 1, 0);
}

// ============================================================================
// V transpose: g_val [h][s][d] f32 -> g_valh [h][d][s] fp16 (32x32 smem tile).
// ============================================================================
__global__ void __launch_bounds__(256) val_transpose()
{
    __shared__ float t[32][33];
    const int h  = blockIdx.z;
    const int d0 = blockIdx.x * 32;
    const int s0 = blockIdx.y * 32;
    const int tx = threadIdx.x & 31;
    const int ty = threadIdx.x >> 5;   // 0..7

    const float* in = g_val + h * SEQ * DDIM;
#pragma unroll
    for (int i = 0; i < 4; i++)
        t[ty + i * 8][tx] = in[(s0 + ty + i * 8) * DDIM + d0 + tx];
    __syncthreads();

    __half* outp = g_valh + h * DDIM * SEQ;
#pragma unroll
    for (int i = 0; i < 4; i++)
        outp[(d0 + ty + i * 8) * SEQ + s0 + tx] =
            __float2half(t[tx][ty + i * 8]);
}

// ============================================================================
// Flash attention. Block: 128 i-rows x one head, 256 threads = 8 warps,
// j-tile 64. Scores tf32 mma; ONLINE-MAX softmax (P = exp(s-m) in (0,1] ->
// fp16-safe by construction, fixing R12's overflow); P stored f16x2; AV in
// fp16 mma (m16n8k16, fp32 accum, alpha-rescaled per tile via smem alphas);
// V staged fp16 [d][j] via cp.async hidden behind the score mma.
// ============================================================================
#define TSTR   68
#define SM_KT  0
#define SM_QT  (128 * TSTR)            // K: 128x68 f32
#define SM_PS  (SM_QT + 64 * TSTR)     // Q: 64x68 f32
#define SM_VT  (SM_PS + 128 * 36)      // P: 128 rows x 36 words (f16x2)
#define SM_AL  (SM_VT + 256 * 36)      // V: 256 rows x 36 words (f16x2)
#define SM_L   (SM_AL + 128)
#define ATTN_SMEM_BYTES ((SM_L + 128) * 4)

__global__ void __launch_bounds__(256) attn_mma()
{
    extern __shared__ float sm[];
    const int tid  = threadIdx.x;
    const int lane = tid & 31;
    const int wid  = tid >> 5;    // 0..7
    const int ty   = lane >> 2;   // 0..7
    const int tq   = lane & 3;    // 0..3
    const int i0   = blockIdx.x * 128;
    const int h    = blockIdx.y;

    const float* kb = g_k + h * SEQ * CDIM;
    const float* qb = g_q + h * SEQ * CDIM;
    const __half* vbb = g_valh + h * DDIM * SEQ;

    // stage K tile once: 128 x 64 floats
#pragma unroll
    for (int i = 0; i < 8; i++) {
        int idx4 = tid + i * 256;            // 0..2047 float4 slots
        int r  = idx4 >> 4;
        int c4 = (idx4 & 15) << 2;
        float4 f = *reinterpret_cast<const float4*>(kb + (i0 + r) * CDIM + c4);
        *reinterpret_cast<float4*>(sm + SM_KT + r * TSTR + c4) = f;
    }

    float acc[8][4][4];
#pragma unroll
    for (int mt = 0; mt < 8; mt++)
#pragma unroll
        for (int nt = 0; nt < 4; nt++)
#pragma unroll
            for (int e = 0; e < 4; e++) acc[mt][nt][e] = 0.0f;

    float rowM[2] = {-1e30f, -1e30f};
    float rowL[2] = {0.0f, 0.0f};

    // prefetch Q tile 0
    float4 qreg[4];
#pragma unroll
    for (int i = 0; i < 4; i++) {
        int idx4 = tid + i * 256;
        int r  = idx4 >> 4;
        int c4 = (idx4 & 15) << 2;
        qreg[i] = *reinterpret_cast<const float4*>(qb + r * CDIM + c4);
    }

    for (int j0 = 0; j0 < SEQ; j0 += 64) {
        // commit prefetched Q tile
#pragma unroll
        for (int i = 0; i < 4; i++) {
            int idx4 = tid + i * 256;
            int r  = idx4 >> 4;
            int c4 = (idx4 & 15) << 2;
            *reinterpret_cast<float4*>(sm + SM_QT + r * TSTR + c4) = qreg[i];
        }
        __syncthreads();   // sync1: Q visible; prev-tile AV done with PS/VT/AL

        // stage V tile fp16 [d][j]: 256 rows x 128B = 2048 x 16B chunks
#pragma unroll
        for (int i = 0; i < 8; i++) {
            int flat = tid + i * 256;        // 0..2047
            int d  = flat >> 3;              // 0..255
            int ch = flat & 7;               // 0..7 (16B chunks of 8 halves)
            cp_async16(smem_u32(sm + SM_VT + d * 36 + ch * 4),
                       vbb + d * SEQ + j0 + ch * 8);
        }
        CP_ASYNC_COMMIT();

        // ---------------- score: all 8 warps, rows [16*wid, 16*wid+16) ----
        float sc[8][4];
#pragma unroll
        for (int nt = 0; nt < 8; nt++)
#pragma unroll
            for (int e = 0; e < 4; e++) sc[nt][e] = 0.0f;

#pragma unroll
        for (int kk = 0; kk < 8; kk++) {
            const float* ka = sm + SM_KT + (wid * 16 + ty) * TSTR + kk * 8 + tq;
            unsigned a0 = __float_as_uint(ka[0]);
            unsigned a2 = __float_as_uint(ka[4]);
            unsigned a1 = __float_as_uint(ka[8 * TSTR]);
            unsigned a3 = __float_as_uint(ka[8 * TSTR + 4]);
#pragma unroll
            for (int nt = 0; nt < 8; nt++) {
                const float* qa = sm + SM_QT + (nt * 8 + ty) * TSTR + kk * 8 + tq;
                unsigned b0 = __float_as_uint(qa[0]);
                unsigned b1 = __float_as_uint(qa[4]);
                mma_tf32(sc[nt], a0, a1, a2, a3, b0, b1);
            }
        }

        // ---------------- online-max softmax: rows rA=16*wid+ty, rB=rA+8 --
        {
            float tmA = -1e30f, tmB = -1e30f;
#pragma unroll
            for (int nt = 0; nt < 8; nt++) {
                tmA = fmaxf(tmA, fmaxf(sc[nt][0], sc[nt][1]));
                tmB = fmaxf(tmB, fmaxf(sc[nt][2], sc[nt][3]));
            }
            tmA = fmaxf(tmA, __shfl_xor_sync(0xffffffffu, tmA, 1));
            tmA = fmaxf(tmA, __shfl_xor_sync(0xffffffffu, tmA, 2));
            tmB = fmaxf(tmB, __shfl_xor_sync(0xffffffffu, tmB, 1));
            tmB = fmaxf(tmB, __shfl_xor_sync(0xffffffffu, tmB, 2));

            float mnA = fmaxf(rowM[0], tmA);
            float mnB = fmaxf(rowM[1], tmB);
            float alA = __expf(rowM[0] - mnA);
            float alB = __expf(rowM[1] - mnB);

            float sumA = 0.0f, sumB = 0.0f;
            const int rA = wid * 16 + ty;
            unsigned* ps = reinterpret_cast<unsigned*>(sm + SM_PS);
#pragma unroll
            for (int nt = 0; nt < 8; nt++) {
                float p0 = __expf(sc[nt][0] - mnA);
                float p1 = __expf(sc[nt][1] - mnA);
                float p2 = __expf(sc[nt][2] - mnB);
                float p3 = __expf(sc[nt][3] - mnB);
                sumA += p0 + p1;
                sumB += p2 + p3;
                ps[rA * 36 + nt * 4 + tq]       = f16x2_pack(p0, p1);
                ps[(rA + 8) * 36 + nt * 4 + tq] = f16x2_pack(p2, p3);
            }
            sumA += __shfl_xor_sync(0xffffffffu, sumA, 1);
            sumA += __shfl_xor_sync(0xffffffffu, sumA, 2);
            sumB += __shfl_xor_sync(0xffffffffu, sumB, 1);
            sumB += __shfl_xor_sync(0xffffffffu, sumB, 2);

            rowL[0] = rowL[0] * alA + sumA;
            rowL[1] = rowL[1] * alB + sumB;
            rowM[0] = mnA;
            rowM[1] = mnB;
            if (tq == 0) {
                sm[SM_AL + rA]     = alA;
                sm[SM_AL + rA + 8] = alB;
            }
        }
        CP_ASYNC_WAIT0();
        __syncthreads();   // sync2: P, alpha, V visible

        // prefetch next Q tile (overlaps AV mma)
        if (j0 + 64 < SEQ) {
#pragma unroll
            for (int i = 0; i < 4; i++) {
                int idx4 = tid + i * 256;
                int r  = idx4 >> 4;
                int c4 = (idx4 & 15) << 2;
                qreg[i] = *reinterpret_cast<const float4*>(
                    qb + (j0 + 64 + r) * CDIM + c4);
            }
        }

        // ---------------- AV fp16: warp owns d-slice [32*wid, 32*wid+32) --
#pragma unroll
        for (int mt = 0; mt < 8; mt++) {
            float aA = sm[SM_AL + mt * 16 + ty];
            float aB = sm[SM_AL + mt * 16 + ty + 8];
#pragma unroll
            for (int nt = 0; nt < 4; nt++) {
                acc[mt][nt][0] *= aA; acc[mt][nt][1] *= aA;
                acc[mt][nt][2] *= aB; acc[mt][nt][3] *= aB;
            }
        }

        const unsigned* vt = reinterpret_cast<const unsigned*>(sm + SM_VT);
        const unsigned* pt = reinterpret_cast<const unsigned*>(sm + SM_PS);
#pragma unroll
        for (int kk = 0; kk < 4; kk++) {
            unsigned bc[4][2];
#pragma unroll
            for (int nt = 0; nt < 4; nt++) {
                const unsigned* p = vt + (wid * 32 + nt * 8 + ty) * 36 + kk * 8 + tq;
                bc[nt][0] = p[0];
                bc[nt][1] = p[4];
            }
#pragma unroll
            for (int mt = 0; mt < 8; mt++) {
                const unsigned* pa = pt + (mt * 16 + ty) * 36 + kk * 8 + tq;
                unsigned a0 = pa[0];
                unsigned a2 = pa[4];
                unsigned a1 = pa[8 * 36];
                unsigned a3 = pa[8 * 36 + 4];
#pragma unroll
                for (int nt = 0; nt < 4; nt++)
                    mma_f16(acc[mt][nt], a0, a1, a2, a3, bc[nt][0], bc[nt][1]);
            }
        }
        // no trailing sync: next iteration's sync1 fences smem reuse
    }

    // publish L, then normalize and write per-head partials
    if (tq == 0) {
        sm[SM_L + wid * 16 + ty]     = rowL[0];
        sm[SM_L + wid * 16 + ty + 8] = rowL[1];
    }
    __syncthreads();

    float* ob = g_part + (h * SEQ + i0) * DDIM + wid * 32;
#pragma unroll
    for (int mt = 0; mt < 8; mt++) {
        float iA = 1.0f / sm[SM_L + mt * 16 + ty];
        float iB = 1.0f / sm[SM_L + mt * 16 + ty + 8];
#pragma unroll
        for (int nt = 0; nt < 4; nt++) {
            float2 wa = make_float2(acc[mt][nt][0] * iA, acc[mt][nt][1] * iA);
            float2 wb = make_float2(acc[mt][nt][2] * iB, acc[mt][nt][3] * iB);
            *reinterpret_cast<float2*>(ob + (mt * 16 + ty) * DDIM + nt * 8 + 2 * tq) = wa;
            *reinterpret_cast<float2*>(ob + (mt * 16 + ty + 8) * DDIM + nt * 8 + 2 * tq) = wb;
        }
    }
}

// ============================================================================
// Sum over the 24 heads.
// ============================================================================
__global__ void __launch_bounds__(256) reduce_heads(float* __restrict__ out)
{
    int i = blockIdx.x * blockDim.x + threadIdx.x;
    float s = 0.0f;
#pragma unroll
    for (int h = 0; h < HEADS; h++)
        s += g_part[h * SEQ * DDIM + i];
    out[i] = s;
}

// ============================================================================
// launch
// ============================================================================
extern "C" void kernel_launch(void* const* d_in, const int* in_sizes, int n_in,
                              void* d_out, int out_size)
{
    (void)in_sizes; (void)n_in; (void)out_size;
    const float* nodes   = (const float*)d_in[0];
    const float* aux     = (const float*)d_in[1];
    const float* rot     = (const float*)d_in[2];
    const float* W_nodes = (const float*)d_in[3];
    const float* b_nodes = (const float*)d_in[4];
    const float* W_aux   = (const float*)d_in[5];
    const float* b_aux   = (const float*)d_in[6];
    const float* W_rot   = (const float*)d_in[7];
    const float* W_val   = (const float*)d_in[8];
    const float* b_val   = (const float*)d_in[9];
    float* out = (float*)d_out;

    cudaFuncSetAttribute(attn_mma,
                         cudaFuncAttributeMaxDynamicSharedMemorySize,
                         ATTN_SMEM_BYTES);

    // tensor-core projections (scatter into head-major k/q/val, tf32-rounded)
    kq_gemm<<<dim3(1024 / 128, SEQ / 128, 3), 256>>>(
        nodes, W_nodes, b_nodes, aux, W_aux, b_aux, rot, W_rot);
    val_gemm<<<dim3(6144 / 128, SEQ / 128), 256>>>(nodes, W_val, b_val);

    // V transpose to fp16 [h][d][s]
    val_transpose<<<dim3(DDIM / 32, SEQ / 32, HEADS), 256>>>();

    // tensor-core flash attention per (128-row i-tile, head)
    attn_mma<<<dim3(SEQ / 128, HEADS), 256, ATTN_SMEM_BYTES>>>();

    // head sum
    reduce_heads<<<(SEQ * DDIM) / 256, 256>>>(out);
}

// round 14
// speedup vs baseline: 6.5323x; 1.1314x over previous
#include <cuda_runtime.h>
#include <cuda_fp16.h>
#include <math.h>

#define SEQ   2048
#define HEADS 24
#define CDIM  64
#define DDIM  256
#define SCALE 0.35355339059327373f   // 1/sqrt(8)

// ---- scratch (static device allocations; no cudaMalloc anywhere) ----
__device__ __half g_k[HEADS * SEQ * CDIM];     // [h][s][c] pre-scaled, fp16
__device__ __half g_q[HEADS * SEQ * CDIM];     // [h][s][c] fp16
__device__ float g_val[HEADS * SEQ * DDIM];    // [h][s][d] f32
__device__ __half g_valh[HEADS * DDIM * SEQ];  // [h][d][s] fp16 transposed
__device__ float g_part[HEADS * SEQ * DDIM];   // [h][s][d] per-head outputs

__device__ __forceinline__ float tf32r(float x) {
    unsigned u;
    asm("cvt.rna.tf32.f32 %0, %1;" : "=r"(u) : "f"(x));
    return __uint_as_float(u);
}

__device__ __forceinline__ unsigned f16x2_pack(float lo, float hi) {
    unsigned r;
    asm("cvt.rn.f16x2.f32 %0, %1, %2;" : "=r"(r) : "f"(hi), "f"(lo));
    return r;
}

__device__ __forceinline__ void mma_tf32(float c[4],
    unsigned a0, unsigned a1, unsigned a2, unsigned a3,
    unsigned b0, unsigned b1)
{
    asm volatile(
        "mma.sync.aligned.m16n8k8.row.col.f32.tf32.tf32.f32 "
        "{%0,%1,%2,%3}, {%4,%5,%6,%7}, {%8,%9}, {%0,%1,%2,%3};"
        : "+f"(c[0]), "+f"(c[1]), "+f"(c[2]), "+f"(c[3])
        : "r"(a0), "r"(a1), "r"(a2), "r"(a3), "r"(b0), "r"(b1));
}

__device__ __forceinline__ void mma_f16(float c[4],
    unsigned a0, unsigned a1, unsigned a2, unsigned a3,
    unsigned b0, unsigned b1)
{
    asm volatile(
        "mma.sync.aligned.m16n8k16.row.col.f32.f16.f16.f32 "
        "{%0,%1,%2,%3}, {%4,%5,%6,%7}, {%8,%9}, {%0,%1,%2,%3};"
        : "+f"(c[0]), "+f"(c[1]), "+f"(c[2]), "+f"(c[3])
        : "r"(a0), "r"(a1), "r"(a2), "r"(a3), "r"(b0), "r"(b1));
}

__device__ __forceinline__ unsigned smem_u32(const void* p) {
    unsigned a;
    asm("{ .reg .u64 t; cvta.to.shared.u64 t, %1; cvt.u32.u64 %0, t; }"
        : "=r"(a) : "l"(p));
    return a;
}

__device__ __forceinline__ void cp_async16(unsigned dst, const void* src) {
    asm volatile("cp.async.cg.shared.global [%0], [%1], 16;"
                 :: "r"(dst), "l"(src));
}
#define CP_ASYNC_COMMIT() asm volatile("cp.async.commit_group;" ::)
#define CP_ASYNC_WAIT0()  asm volatile("cp.async.wait_group 0;" ::: "memory")

// ============================================================================
// Tensor-core projection GEMM (structure unchanged; k/q now stored fp16)
// ============================================================================
#define GSTR 36

__device__ __forceinline__ void gscatter(int mode, int head_base,
                                         int s, int n, float v)
{
    if (mode == 0) {
        int h = head_base + (n >> 7);
        int c = n & 127;
        if (c < 64) g_k[(h * SEQ + s) * CDIM + c] = __float2half(v * SCALE);
        else        g_q[(h * SEQ + s) * CDIM + (c - 64)] = __float2half(v);
    } else {
        int h = n >> 8;
        int d = n & 255;
        g_val[(h * SEQ + s) * DDIM + d] = tf32r(v);
    }
}

__device__ __forceinline__ void mma_gemm(
    const float* __restrict__ A, const float* __restrict__ W,
    const float* __restrict__ bias, int K, int mode, int head_base)
{
    __shared__ float As[128 * GSTR];
    __shared__ float Bs[128 * GSTR];

    const int tid  = threadIdx.x;
    const int lane = tid & 31;
    const int wid  = tid >> 5;
    const int ty   = lane >> 2;
    const int tq   = lane & 3;
    const int wm   = wid & 3;
    const int wn   = wid >> 2;
    const int row0 = blockIdx.y * 128;
    const int col0 = blockIdx.x * 128;

    float acc[2][8][4];
#pragma unroll
    for (int mt = 0; mt < 2; mt++)
#pragma unroll
        for (int nt = 0; nt < 8; nt++)
#pragma unroll
            for (int e = 0; e < 4; e++) acc[mt][nt][e] = 0.0f;

    for (int k0 = 0; k0 < K; k0 += 32) {
        __syncthreads();
        const int rem = K - k0;
#pragma unroll
        for (int i = 0; i < 4; i++) {
            int flat = tid + i * 256;
            int r  = flat >> 3;
            int c4 = (flat & 7) * 4;
            float4 fa = make_float4(0.f, 0.f, 0.f, 0.f);
            float4 fb = make_float4(0.f, 0.f, 0.f, 0.f);
            const float* pa = A + (row0 + r) * K + k0 + c4;
            const float* pb = W + (col0 + r) * K + k0 + c4;
            if (c4 + 4 <= rem) {
                fa = *reinterpret_cast<const float4*>(pa);
                fb = *reinterpret_cast<const float4*>(pb);
            } else {
                if (c4 + 0 < rem) { fa.x = pa[0]; fb.x = pb[0]; }
                if (c4 + 1 < rem) { fa.y = pa[1]; fb.y = pb[1]; }
                if (c4 + 2 < rem) { fa.z = pa[2]; fb.z = pb[2]; }
                if (c4 + 3 < rem) { fa.w = pa[3]; fb.w = pb[3]; }
            }
            fa.x = tf32r(fa.x); fa.y = tf32r(fa.y);
            fa.z = tf32r(fa.z); fa.w = tf32r(fa.w);
            fb.x = tf32r(fb.x); fb.y = tf32r(fb.y);
            fb.z = tf32r(fb.z); fb.w = tf32r(fb.w);
            *reinterpret_cast<float4*>(As + r * GSTR + c4) = fa;
            *reinterpret_cast<float4*>(Bs + r * GSTR + c4) = fb;
        }
        __syncthreads();

#pragma unroll
        for (int kk = 0; kk < 4; kk++) {
            unsigned b0[8], b1[8];
#pragma unroll
            for (int nt = 0; nt < 8; nt++) {
                const float* pb = Bs + (wn * 64 + nt * 8 + ty) * GSTR + kk * 8 + tq;
                b0[nt] = __float_as_uint(pb[0]);
                b1[nt] = __float_as_uint(pb[4]);
            }
#pragma unroll
            for (int mt = 0; mt < 2; mt++) {
                const float* pa = As + (wm * 32 + mt * 16 + ty) * GSTR + kk * 8 + tq;
                unsigned a0 = __float_as_uint(pa[0]);
                unsigned a2 = __float_as_uint(pa[4]);
                unsigned a1 = __float_as_uint(pa[8 * GSTR]);
                unsigned a3 = __float_as_uint(pa[8 * GSTR + 4]);
#pragma unroll
                for (int nt = 0; nt < 8; nt++)
                    mma_tf32(acc[mt][nt], a0, a1, a2, a3, b0[nt], b1[nt]);
            }
        }
    }

#pragma unroll
    for (int nt = 0; nt < 8; nt++) {
        int n = col0 + wn * 64 + nt * 8 + 2 * tq;
        float2 bb = make_float2(0.f, 0.f);
        if (bias) bb = *reinterpret_cast<const float2*>(bias + n);
#pragma unroll
        for (int mt = 0; mt < 2; mt++) {
            int s0 = row0 + wm * 32 + mt * 16 + ty;
            gscatter(mode, head_base, s0,     n,     acc[mt][nt][0] + bb.x);
            gscatter(mode, head_base, s0,     n + 1, acc[mt][nt][1] + bb.y);
            gscatter(mode, head_base, s0 + 8, n,     acc[mt][nt][2] + bb.x);
            gscatter(mode, head_base, s0 + 8, n + 1, acc[mt][nt][3] + bb.y);
        }
    }
}

__global__ void __launch_bounds__(256, 2) kq_gemm(
    const float* __restrict__ nodes, const float* __restrict__ Wn, const float* __restrict__ bn,
    const float* __restrict__ aux,   const float* __restrict__ Wa, const float* __restrict__ ba,
    const float* __restrict__ rot,   const float* __restrict__ Wr)
{
    if (blockIdx.z == 0)       mma_gemm(nodes, Wn, bn,      256, 0, 0);
    else if (blockIdx.z == 1)  mma_gemm(aux,   Wa, ba,      64,  0, 8);
    else                       mma_gemm(rot,   Wr, nullptr, 4,   0, 16);
}

__global__ void __launch_bounds__(256, 2) val_gemm(
    const float* __restrict__ nodes, const float* __restrict__ Wv,
    const float* __restrict__ bv)
{
    mma_gemm(nodes, Wv, bv, 256, 1, 0);
}

// ============================================================================
// V transpose: g_val [h][s][d] f32 -> g_valh [h][d][s] fp16 (32x32 smem tile).
// ============================================================================
__global__ void __launch_bounds__(256) val_transpose()
{
    __shared__ float t[32][33];
    const int h  = blockIdx.z;
    const int d0 = blockIdx.x * 32;
    const int s0 = blockIdx.y * 32;
    const int tx = threadIdx.x & 31;
    const int ty = threadIdx.x >> 5;   // 0..7

    const float* in = g_val + h * SEQ * DDIM;
#pragma unroll
    for (int i = 0; i < 4; i++)
        t[ty + i * 8][tx] = in[(s0 + ty + i * 8) * DDIM + d0 + tx];
    __syncthreads();

    __half* outp = g_valh + h * DDIM * SEQ;
#pragma unroll
    for (int i = 0; i < 4; i++)
        outp[(d0 + ty + i * 8) * SEQ + s0 + tx] =
            __float2half(t[tx][ty + i * 8]);
}

// ============================================================================
// Flash attention, all-fp16 operands, fp32 accum, online-max softmax.
// Block: 128 i-rows x one head, 256 threads = 8 warps, j-tile 64.
// SINGLE __syncthreads per tile via parity double-buffering of Q/P/V/alpha:
//   commit Q(t+1)->buf[(t+1)&1]; cp.async V(t)->buf[t&1]; score(t) (fp16 mma,
//   Qbuf[t&1], synced at t-1); softmax -> P/alpha buf[t&1]; wait; sync; AV(t).
// Hazards: any parity-p buffer's next write is barrier-separated from its
// last read (Q(t+1) parity == Q(t-1), last read by score(t-1) pre-sync(t-1);
// AV(t-1) reads the opposite parity of P/V).
// All smem rows stride 36 words -> fragment LDS hit bank 4*ty+tq: conflict-free.
// ============================================================================
#define SM_K   0                       // K: 128 x 36 words (f16x2)
#define SM_Q   (128 * 36)              // Q: 2 bufs x 64 x 36
#define SM_P   (SM_Q + 2 * 64 * 36)    // P: 2 bufs x 128 x 36
#define SM_V   (SM_P + 2 * 128 * 36)   // V: 2 bufs x 256 x 36
#define SM_A   (SM_V + 2 * 256 * 36)   // alpha: 2 x 128
#define SM_L   (SM_A + 2 * 128)
#define ATTN_SMEM_BYTES ((SM_L + 128) * 4)

__global__ void __launch_bounds__(256) attn_mma()
{
    extern __shared__ float sm[];
    const int tid  = threadIdx.x;
    const int lane = tid & 31;
    const int wid  = tid >> 5;    // 0..7
    const int ty   = lane >> 2;   // 0..7
    const int tq   = lane & 3;    // 0..3
    const int i0   = blockIdx.x * 128;
    const int h    = blockIdx.y;

    const __half* kb  = g_k + h * SEQ * CDIM;
    const __half* qb  = g_q + h * SEQ * CDIM;
    const __half* vbb = g_valh + h * DDIM * SEQ;

    // prologue: stage K tile (128 rows x 8 x 16B) and Q tile 0 (64 rows)
#pragma unroll
    for (int i = 0; i < 4; i++) {
        int flat = tid + i * 256;          // 0..1023
        int r  = flat >> 3;
        int ch = flat & 7;
        uint4 v = *reinterpret_cast<const uint4*>(kb + (i0 + r) * CDIM + ch * 8);
        *reinterpret_cast<uint4*>(sm + SM_K + r * 36 + ch * 4) = v;
    }
#pragma unroll
    for (int i = 0; i < 2; i++) {
        int flat = tid + i * 256;          // 0..511
        int r  = flat >> 3;
        int ch = flat & 7;
        uint4 v = *reinterpret_cast<const uint4*>(qb + r * CDIM + ch * 8);
        *reinterpret_cast<uint4*>(sm + SM_Q + r * 36 + ch * 4) = v;
    }
    __syncthreads();

    // prefetch Q tile 1 into registers
    uint4 qreg[2];
#pragma unroll
    for (int i = 0; i < 2; i++) {
        int flat = tid + i * 256;
        int r  = flat >> 3;
        int ch = flat & 7;
        qreg[i] = *reinterpret_cast<const uint4*>(qb + (64 + r) * CDIM + ch * 8);
    }

    float acc[8][4][4];
#pragma unroll
    for (int mt = 0; mt < 8; mt++)
#pragma unroll
        for (int nt = 0; nt < 4; nt++)
#pragma unroll
            for (int e = 0; e < 4; e++) acc[mt][nt][e] = 0.0f;

    float rowM[2] = {-1e30f, -1e30f};
    float rowL[2] = {0.0f, 0.0f};

    for (int t = 0; t < SEQ / 64; t++) {
        const int j0  = t * 64;
        const int par = t & 1;
        const int nxt = par ^ 1;

        // commit prefetched Q(t+1) into the other buffer (read after sync(t))
#pragma unroll
        for (int i = 0; i < 2; i++) {
            int flat = tid + i * 256;
            int r  = flat >> 3;
            int ch = flat & 7;
            *reinterpret_cast<uint4*>(sm + SM_Q + nxt * (64 * 36) + r * 36 + ch * 4) = qreg[i];
        }

        // stage V(t) fp16 [d][j] into parity buffer: 2048 x 16B chunks
        {
            float* vdst = sm + SM_V + par * (256 * 36);
#pragma unroll
            for (int i = 0; i < 8; i++) {
                int flat = tid + i * 256;    // 0..2047
                int d  = flat >> 3;          // 0..255
                int ch = flat & 7;
                cp_async16(smem_u32(vdst + d * 36 + ch * 4),
                           vbb + d * SEQ + j0 + ch * 8);
            }
        }
        CP_ASYNC_COMMIT();

        // ---------------- score fp16: warp w owns rows [16w,16w+16) -------
        float sc[8][4];
#pragma unroll
        for (int nt = 0; nt < 8; nt++)
#pragma unroll
            for (int e = 0; e < 4; e++) sc[nt][e] = 0.0f;

        const unsigned* Kp = reinterpret_cast<const unsigned*>(sm + SM_K);
        const unsigned* Qp = reinterpret_cast<const unsigned*>(sm + SM_Q + par * (64 * 36));
#pragma unroll
        for (int kk = 0; kk < 4; kk++) {
            const unsigned* pa = Kp + (wid * 16 + ty) * 36 + kk * 8 + tq;
            unsigned a0 = pa[0];
            unsigned a2 = pa[4];
            unsigned a1 = pa[8 * 36];
            unsigned a3 = pa[8 * 36 + 4];
#pragma unroll
            for (int nt = 0; nt < 8; nt++) {
                const unsigned* qa = Qp + (nt * 8 + ty) * 36 + kk * 8 + tq;
                mma_f16(sc[nt], a0, a1, a2, a3, qa[0], qa[4]);
            }
        }

        // ---------------- online-max softmax: rows rA=16*wid+ty, rB=rA+8 --
        {
            float tmA = -1e30f, tmB = -1e30f;
#pragma unroll
            for (int nt = 0; nt < 8; nt++) {
                tmA = fmaxf(tmA, fmaxf(sc[nt][0], sc[nt][1]));
                tmB = fmaxf(tmB, fmaxf(sc[nt][2], sc[nt][3]));
            }
            tmA = fmaxf(tmA, __shfl_xor_sync(0xffffffffu, tmA, 1));
            tmA = fmaxf(tmA, __shfl_xor_sync(0xffffffffu, tmA, 2));
            tmB = fmaxf(tmB, __shfl_xor_sync(0xffffffffu, tmB, 1));
            tmB = fmaxf(tmB, __shfl_xor_sync(0xffffffffu, tmB, 2));

            float mnA = fmaxf(rowM[0], tmA);
            float mnB = fmaxf(rowM[1], tmB);
            float alA = __expf(rowM[0] - mnA);
            float alB = __expf(rowM[1] - mnB);

            float sumA = 0.0f, sumB = 0.0f;
            const int rA = wid * 16 + ty;
            unsigned* ps = reinterpret_cast<unsigned*>(sm + SM_P + par * (128 * 36));
#pragma unroll
            for (int nt = 0; nt < 8; nt++) {
                float p0 = __expf(sc[nt][0] - mnA);
                float p1 = __expf(sc[nt][1] - mnA);
                float p2 = __expf(sc[nt][2] - mnB);
                float p3 = __expf(sc[nt][3] - mnB);
                sumA += p0 + p1;
                sumB += p2 + p3;
                ps[rA * 36 + nt * 4 + tq]       = f16x2_pack(p0, p1);
                ps[(rA + 8) * 36 + nt * 4 + tq] = f16x2_pack(p2, p3);
            }
            sumA += __shfl_xor_sync(0xffffffffu, sumA, 1);
            sumA += __shfl_xor_sync(0xffffffffu, sumA, 2);
            sumB += __shfl_xor_sync(0xffffffffu, sumB, 1);
            sumB += __shfl_xor_sync(0xffffffffu, sumB, 2);

            rowL[0] = rowL[0] * alA + sumA;
            rowL[1] = rowL[1] * alB + sumB;
            rowM[0] = mnA;
            rowM[1] = mnB;
            if (tq == 0) {
                sm[SM_A + par * 128 + rA]     = alA;
                sm[SM_A + par * 128 + rA + 8] = alB;
            }
        }

        // prefetch Q(t+2) into registers (bounded)
        if (j0 + 128 < SEQ) {
#pragma unroll
            for (int i = 0; i < 2; i++) {
                int flat = tid + i * 256;
                int r  = flat >> 3;
                int ch = flat & 7;
                qreg[i] = *reinterpret_cast<const uint4*>(
                    qb + (j0 + 128 + r) * CDIM + ch * 8);
            }
        }

        CP_ASYNC_WAIT0();
        __syncthreads();   // the ONE barrier: P, alpha, V(t), Q(t+1) visible

        // ---------------- AV fp16: warp owns d-slice [32*wid, 32*wid+32) --
        const float* al = sm + SM_A + par * 128;
#pragma unroll
        for (int mt = 0; mt < 8; mt++) {
            float aA = al[mt * 16 + ty];
            float aB = al[mt * 16 + ty + 8];
#pragma unroll
            for (int nt = 0; nt < 4; nt++) {
                acc[mt][nt][0] *= aA; acc[mt][nt][1] *= aA;
                acc[mt][nt][2] *= aB; acc[mt][nt][3] *= aB;
            }
        }

        const unsigned* vt = reinterpret_cast<const unsigned*>(sm + SM_V + par * (256 * 36));
        const unsigned* pt = reinterpret_cast<const unsigned*>(sm + SM_P + par * (128 * 36));
#pragma unroll
        for (int kk = 0; kk < 4; kk++) {
            unsigned bc[4][2];
#pragma unroll
            for (int nt = 0; nt < 4; nt++) {
                const unsigned* p = vt + (wid * 32 + nt * 8 + ty) * 36 + kk * 8 + tq;
                bc[nt][0] = p[0];
                bc[nt][1] = p[4];
            }
#pragma unroll
            for (int mt = 0; mt < 8; mt++) {
                const unsigned* pa = pt + (mt * 16 + ty) * 36 + kk * 8 + tq;
                unsigned a0 = pa[0];
                unsigned a2 = pa[4];
                unsigned a1 = pa[8 * 36];
                unsigned a3 = pa[8 * 36 + 4];
#pragma unroll
                for (int nt = 0; nt < 4; nt++)
                    mma_f16(acc[mt][nt], a0, a1, a2, a3, bc[nt][0], bc[nt][1]);
            }
        }
        // no trailing sync: parity buffering + next tile's barrier protect reuse
    }

    // publish L, then normalize and write per-head partials
    if (tq == 0) {
        sm[SM_L + wid * 16 + ty]     = rowL[0];
        sm[SM_L + wid * 16 + ty + 8] = rowL[1];
    }
    __syncthreads();

    float* ob = g_part + (h * SEQ + i0) * DDIM + wid * 32;
#pragma unroll
    for (int mt = 0; mt < 8; mt++) {
        float iA = 1.0f / sm[SM_L + mt * 16 + ty];
        float iB = 1.0f / sm[SM_L + mt * 16 + ty + 8];
#pragma unroll
        for (int nt = 0; nt < 4; nt++) {
            float2 wa = make_float2(acc[mt][nt][0] * iA, acc[mt][nt][1] * iA);
            float2 wb = make_float2(acc[mt][nt][2] * iB, acc[mt][nt][3] * iB);
            *reinterpret_cast<float2*>(ob + (mt * 16 + ty) * DDIM + nt * 8 + 2 * tq) = wa;
            *reinterpret_cast<float2*>(ob + (mt * 16 + ty + 8) * DDIM + nt * 8 + 2 * tq) = wb;
        }
    }
}

// ============================================================================
// Sum over the 24 heads.
// ============================================================================
__global__ void __launch_bounds__(256) reduce_heads(float* __restrict__ out)
{
    int i = blockIdx.x * blockDim.x + threadIdx.x;
    float s = 0.0f;
#pragma unroll
    for (int h = 0; h < HEADS; h++)
        s += g_part[h * SEQ * DDIM + i];
    out[i] = s;
}

// ============================================================================
// launch
// ============================================================================
extern "C" void kernel_launch(void* const* d_in, const int* in_sizes, int n_in,
                              void* d_out, int out_size)
{
    (void)in_sizes; (void)n_in; (void)out_size;
    const float* nodes   = (const float*)d_in[0];
    const float* aux     = (const float*)d_in[1];
    const float* rot     = (const float*)d_in[2];
    const float* W_nodes = (const float*)d_in[3];
    const float* b_nodes = (const float*)d_in[4];
    const float* W_aux   = (const float*)d_in[5];
    const float* b_aux   = (const float*)d_in[6];
    const float* W_rot   = (const float*)d_in[7];
    const float* W_val   = (const float*)d_in[8];
    const float* b_val   = (const float*)d_in[9];
    float* out = (float*)d_out;

    cudaFuncSetAttribute(attn_mma,
                         cudaFuncAttributeMaxDynamicSharedMemorySize,
                         ATTN_SMEM_BYTES);

    // tensor-core projections (k/q fp16, val tf32)
    kq_gemm<<<dim3(1024 / 128, SEQ / 128, 3), 256>>>(
        nodes, W_nodes, b_nodes, aux, W_aux, b_aux, rot, W_rot);
    val_gemm<<<dim3(6144 / 128, SEQ / 128), 256>>>(nodes, W_val, b_val);

    // V transpose to fp16 [h][d][s]
    val_transpose<<<dim3(DDIM / 32, SEQ / 32, HEADS), 256>>>();

    // tensor-core flash attention per (128-row i-tile, head)
    attn_mma<<<dim3(SEQ / 128, HEADS), 256, ATTN_SMEM_BYTES>>>();

    // head sum
    reduce_heads<<<(SEQ * DDIM) / 256, 256>>>(out);
}